// round 9
// baseline (speedup 1.0000x reference)
#include <cuda_runtime.h>
#include <cuda_bf16.h>
#include <math.h>

// Problem constants
#define BB 2
#define SS 2048
#define DD 2048
#define HH 16
#define NOPE 128
#define ROPE_D 64
#define VD 128
#define KV_RANK 512
#define Q_RANK 1536
#define QH (NOPE + ROPE_D)   // 192
#define KVH (NOPE + VD)      // 256
#define RTOT (BB * SS)       // 4096 rows

// ---------------- scratch (device globals, no allocation) ----------------
__device__ float g_cq [RTOT * Q_RANK];
__device__ float g_q  [RTOT * (HH * QH)];
__device__ float g_ckv[RTOT * (KV_RANK + ROPE_D)];
__device__ float g_kva[RTOT * KV_RANK];
__device__ float g_kpe[RTOT * ROPE_D];
__device__ float g_kv [RTOT * (HH * KVH)];
__device__ float g_o  [RTOT * (HH * VD)];
__device__ float g_cos[SS * (ROPE_D / 2)];
__device__ float g_sin[SS * (ROPE_D / 2)];
// tf32-rounded operand copies
__device__ float g_xr  [RTOT * DD];
__device__ float g_wdq [DD * Q_RANK];
__device__ float g_wuq [Q_RANK * HH * QH];
__device__ float g_wdkv[DD * (KV_RANK + ROPE_D)];
__device__ float g_wukv[KV_RANK * HH * KVH];
__device__ float g_wo  [HH * VD * DD];

// ---------------- helpers -------------------------------------------------
__device__ __forceinline__ unsigned f2tf32(float x) {
    unsigned r;
    asm("cvt.rna.tf32.f32 %0, %1;" : "=r"(r) : "f"(x));
    return r;
}
__device__ __forceinline__ float roundtf(float x) {
    return __uint_as_float(f2tf32(x));
}

__device__ __forceinline__ void mma_tf32(float c[4], const unsigned a[4], const unsigned b[2]) {
    asm volatile(
        "mma.sync.aligned.m16n8k8.row.col.f32.tf32.tf32.f32 "
        "{%0,%1,%2,%3}, {%4,%5,%6,%7}, {%8,%9}, {%0,%1,%2,%3};\n"
        : "+f"(c[0]), "+f"(c[1]), "+f"(c[2]), "+f"(c[3])
        : "r"(a[0]), "r"(a[1]), "r"(a[2]), "r"(a[3]), "r"(b[0]), "r"(b[1]));
}

__device__ __forceinline__ void cpasync16(void* dst_smem, const void* src) {
    unsigned d = (unsigned)__cvta_generic_to_shared(dst_smem);
    asm volatile("cp.async.cg.shared.global [%0], [%1], 16;\n" :: "r"(d), "l"(src));
}
#define CP_COMMIT() asm volatile("cp.async.commit_group;\n")
#define CP_WAIT(n)  asm volatile("cp.async.wait_group %0;\n" :: "n"(n))

// ---------------- tf32 pre-round pass ------------------------------------
__global__ void cvt_k(const float4* __restrict__ in, float4* __restrict__ out, int n4)
{
    int i = blockIdx.x * blockDim.x + threadIdx.x;
    int stride = gridDim.x * blockDim.x;
    for (; i < n4; i += stride) {
        float4 v = in[i];
        v.x = roundtf(v.x); v.y = roundtf(v.y);
        v.z = roundtf(v.z); v.w = roundtf(v.w);
        out[i] = v;
    }
}

// ---------------- tf32 tensor-core GEMM: C = A(MxK) @ B(KxN), row-major ---
// A and B must already be tf32-rounded. 128x128 block tile, BK=32,
// 128 threads (4 warps as 2x2), warp tile 64x64, double-buffered cp.async.
#define TBM 128
#define TBN 128
#define TBK 32
#define AS_STR 36
#define BS_STR 136
#define AS_ELE (TBM * AS_STR)
#define BS_ELE (TBK * BS_STR)
#define TG_SMEM ((2 * AS_ELE + 2 * BS_ELE) * 4)

__global__ __launch_bounds__(128, 2) void tgemm_k(
    const float* __restrict__ A, const float* __restrict__ B,
    float* __restrict__ C, int M, int N, int K)
{
    extern __shared__ float sm[];
    float* As[2] = {sm, sm + AS_ELE};
    float* Bs[2] = {sm + 2 * AS_ELE, sm + 2 * AS_ELE + BS_ELE};

    const int n0 = blockIdx.x * TBN;
    const int m0 = blockIdx.y * TBM;
    const int tid  = threadIdx.x;
    const int lane = tid & 31;
    const int warp = tid >> 5;
    const int wm = warp & 1;
    const int wn = warp >> 1;
    const int g  = lane >> 2;
    const int tg = lane & 3;

    const int aRow  = tid >> 3;
    const int aCol4 = (tid & 7) * 4;
    const int bRow  = tid >> 5;
    const int bCol  = (tid & 31) * 4;
    const int bColC = (n0 + bCol < N) ? (n0 + bCol) : (N - 4);

    float acc[4][8][4];
#pragma unroll
    for (int i = 0; i < 4; i++)
#pragma unroll
        for (int j = 0; j < 8; j++)
#pragma unroll
            for (int e = 0; e < 4; e++) acc[i][j][e] = 0.f;

    const int nt = K / TBK;

    {
        const float* Asrc = A + (size_t)(m0 + aRow) * K + aCol4;
        float* Adst = As[0] + aRow * AS_STR + aCol4;
#pragma unroll
        for (int s = 0; s < 8; s++)
            cpasync16(Adst + s * 16 * AS_STR, Asrc + (size_t)s * 16 * K);
        const float* Bsrc = B + (size_t)bRow * N + bColC;
        float* Bdst = Bs[0] + bRow * BS_STR + bCol;
#pragma unroll
        for (int s = 0; s < 8; s++)
            cpasync16(Bdst + s * 4 * BS_STR, Bsrc + (size_t)s * 4 * N);
        CP_COMMIT();
    }

    for (int t = 0; t < nt; t++) {
        const int buf = t & 1;
        if (t + 1 < nt) {
            const int kn = (t + 1) * TBK;
            const float* Asrc = A + (size_t)(m0 + aRow) * K + kn + aCol4;
            float* Adst = As[buf ^ 1] + aRow * AS_STR + aCol4;
#pragma unroll
            for (int s = 0; s < 8; s++)
                cpasync16(Adst + s * 16 * AS_STR, Asrc + (size_t)s * 16 * K);
            const float* Bsrc = B + (size_t)(kn + bRow) * N + bColC;
            float* Bdst = Bs[buf ^ 1] + bRow * BS_STR + bCol;
#pragma unroll
            for (int s = 0; s < 8; s++)
                cpasync16(Bdst + s * 4 * BS_STR, Bsrc + (size_t)s * 4 * N);
            CP_COMMIT();
            CP_WAIT(1);
        } else {
            CP_WAIT(0);
        }
        __syncthreads();

        const float* Ab = As[buf];
        const float* Bb = Bs[buf];
#pragma unroll
        for (int kk = 0; kk < 4; kk++) {
            const int kr = kk * 8;
            unsigned af[4][4], bf[8][2];
#pragma unroll
            for (int i = 0; i < 4; i++) {
                const int r = wm * 64 + i * 16;
                af[i][0] = __float_as_uint(Ab[(r + g) * AS_STR + kr + tg]);
                af[i][1] = __float_as_uint(Ab[(r + g + 8) * AS_STR + kr + tg]);
                af[i][2] = __float_as_uint(Ab[(r + g) * AS_STR + kr + tg + 4]);
                af[i][3] = __float_as_uint(Ab[(r + g + 8) * AS_STR + kr + tg + 4]);
            }
#pragma unroll
            for (int j = 0; j < 8; j++) {
                const int cb = wn * 64 + j * 8;
                bf[j][0] = __float_as_uint(Bb[(kr + tg) * BS_STR + cb + g]);
                bf[j][1] = __float_as_uint(Bb[(kr + tg + 4) * BS_STR + cb + g]);
            }
#pragma unroll
            for (int i = 0; i < 4; i++)
#pragma unroll
                for (int j = 0; j < 8; j++)
                    mma_tf32(acc[i][j], af[i], bf[j]);
        }
        __syncthreads();
    }

#pragma unroll
    for (int i = 0; i < 4; i++) {
        const int r0 = m0 + wm * 64 + i * 16 + g;
#pragma unroll
        for (int j = 0; j < 8; j++) {
            const int c = n0 + wn * 64 + j * 8 + 2 * tg;
            if (c < N) {
                *(float2*)(C + (size_t)r0 * N + c) = make_float2(acc[i][j][0], acc[i][j][1]);
                *(float2*)(C + (size_t)(r0 + 8) * N + c) = make_float2(acc[i][j][2], acc[i][j][3]);
            }
        }
    }
}

// ---------------- RMSNorm (tf32-rounded output) --------------------------
__global__ void rmsnorm_k(const float* in, float* out, const float* __restrict__ w,
                          int cols, int in_stride, int out_stride)
{
    const int row = blockIdx.x;
    const float* xi = in + (size_t)row * in_stride;
    float s = 0.f;
    for (int c = threadIdx.x; c < cols; c += blockDim.x) {
        float v = xi[c];
        s += v * v;
    }
    __shared__ float red[8];
#pragma unroll
    for (int o = 16; o > 0; o >>= 1) s += __shfl_down_sync(0xffffffffu, s, o);
    int warp = threadIdx.x >> 5, lane = threadIdx.x & 31;
    if (lane == 0) red[warp] = s;
    __syncthreads();
    if (warp == 0) {
        s = (lane < (blockDim.x >> 5)) ? red[lane] : 0.f;
#pragma unroll
        for (int o = 4; o > 0; o >>= 1) s += __shfl_down_sync(0xffffffffu, s, o);
        if (lane == 0) red[0] = s;
    }
    __syncthreads();
    float r = rsqrtf(red[0] / (float)cols + 1e-6f);
    float* yo = out + (size_t)row * out_stride;
    for (int c = threadIdx.x; c < cols; c += blockDim.x)
        yo[c] = roundtf(xi[c] * r * w[c]);
}

// ---------------- RoPE ---------------------------------------------------
__global__ void rope_table_k(float* ct, float* st)
{
    int s = blockIdx.x, i = threadIdx.x;
    double inv = exp(-((double)(2 * i) / 64.0) * log(10000.0));
    double ang = (double)s * inv;
    ct[s * 32 + i] = (float)cos(ang);
    st[s * 32 + i] = (float)sin(ang);
}

__global__ void rope_q_k(float* Q, const float* __restrict__ ct, const float* __restrict__ st)
{
    int bs = blockIdx.x;
    int s = bs & (SS - 1);
    int i = threadIdx.x;
    int h = threadIdx.y;
    size_t base = ((size_t)bs * HH + h) * QH + NOPE;
    float c = ct[s * 32 + i], sn = st[s * 32 + i];
    float x1 = Q[base + i], x2 = Q[base + 32 + i];
    Q[base + i]      = x1 * c - x2 * sn;
    Q[base + 32 + i] = x2 * c + x1 * sn;
}

__global__ void rope_k_k(const float* __restrict__ CKV, float* KPE,
                         const float* __restrict__ ct, const float* __restrict__ st)
{
    int bs = blockIdx.x;
    int s = bs & (SS - 1);
    int i = threadIdx.x;
    const float* src = CKV + (size_t)bs * (KV_RANK + ROPE_D) + KV_RANK;
    float c = ct[s * 32 + i], sn = st[s * 32 + i];
    float x1 = src[i], x2 = src[32 + i];
    KPE[(size_t)bs * ROPE_D + i]      = x1 * c - x2 * sn;
    KPE[(size_t)bs * ROPE_D + 32 + i] = x2 * c + x1 * sn;
}

// ---------------- tf32 tensor-core causal flash attention ----------------
// Block: (b, h, 128-query tile). 256 threads = 8 warps; warp w owns query
// rows q0 + 16w + {g, g+8}. Q persistent in registers (raw tf32-exact bits;
// inputs pre-rounded). K/V staged raw by double-buffered cp.async in 32-key
// tiles; scale applied to scores post-MMA in fp32.
#define FBM 128
#define FBN 32
#define KS_STR 196
#define VS_STR 136
#define PS_STR 68
#define KS_ELE (FBN * KS_STR)
#define VS_ELE (FBN * VS_STR)
#define FLASH_SMEM ((2 * KS_ELE + 2 * VS_ELE + FBM * PS_STR) * 4)

__global__ __launch_bounds__(256) void flash_k(
    const float* __restrict__ Q, const float* __restrict__ KV,
    const float* __restrict__ KPE, float* __restrict__ O)
{
    extern __shared__ unsigned smu[];
    unsigned* Ksb[2] = {smu, smu + KS_ELE};
    unsigned* Vsb[2] = {smu + 2 * KS_ELE, smu + 2 * KS_ELE + VS_ELE};
    unsigned* Ps = smu + 2 * KS_ELE + 2 * VS_ELE;   // [128][68]

    const int q0 = blockIdx.x * FBM;
    const int h = blockIdx.y;
    const int b = blockIdx.z;
    const int t = threadIdx.x;
    const int warp = t >> 5;
    const int lane = t & 31;
    const int g = lane >> 2;
    const int tg = lane & 3;
    const int row0 = warp * 16 + g;
    const float scale = rsqrtf((float)QH);

    // persistent Q fragments — raw bits, already tf32-exact
    unsigned aq[24][4];
    {
        const float* qp0 = Q + ((size_t)(b * SS + q0 + row0) * HH + h) * QH;
        const float* qp1 = qp0 + (size_t)8 * HH * QH;
#pragma unroll
        for (int kc = 0; kc < 24; kc++) {
            aq[kc][0] = __float_as_uint(qp0[kc * 8 + tg]);
            aq[kc][1] = __float_as_uint(qp1[kc * 8 + tg]);
            aq[kc][2] = __float_as_uint(qp0[kc * 8 + tg + 4]);
            aq[kc][3] = __float_as_uint(qp1[kc * 8 + tg + 4]);
        }
    }

    float oacc[16][4];
#pragma unroll
    for (int i = 0; i < 16; i++)
#pragma unroll
        for (int e = 0; e < 4; e++) oacc[i][e] = 0.f;
    float m0 = -3.0e38f, m1 = -3.0e38f, l0 = 0.f, l1 = 0.f;

    // cp.async tile loader: 8 threads per key row
    const int lr = t >> 3;      // key row 0..31
    const int q8 = t & 7;
    const int ntiles = (q0 + FBM) / FBN;

    // prologue: tile 0 into buffer 0
    {
        const float4* kn = (const float4*)(KV + ((size_t)(b * SS + lr) * HH + h) * KVH);
        const float4* kp = (const float4*)(KPE + (size_t)(b * SS + lr) * ROPE_D);
        unsigned* kd = Ksb[0] + lr * KS_STR;
        unsigned* vd = Vsb[0] + lr * VS_STR;
#pragma unroll
        for (int i = 0; i < 6; i++) {
            int d4 = q8 * 6 + i;
            cpasync16(kd + d4 * 4, (d4 < 32) ? (const void*)(kn + d4) : (const void*)(kp + d4 - 32));
        }
#pragma unroll
        for (int i = 0; i < 4; i++) {
            int d4 = q8 * 4 + i;
            cpasync16(vd + d4 * 4, kn + 32 + d4);
        }
        CP_COMMIT();
    }

    for (int tile = 0; tile < ntiles; tile++) {
        const int k0 = tile * FBN;
        const int buf = tile & 1;
        CP_WAIT(0);
        __syncthreads();

        // prefetch next tile into the other buffer
        if (tile + 1 < ntiles) {
            const int kn0 = (tile + 1) * FBN;
            const float4* kn = (const float4*)(KV + ((size_t)(b * SS + kn0 + lr) * HH + h) * KVH);
            const float4* kp = (const float4*)(KPE + (size_t)(b * SS + kn0 + lr) * ROPE_D);
            unsigned* kd = Ksb[buf ^ 1] + lr * KS_STR;
            unsigned* vd = Vsb[buf ^ 1] + lr * VS_STR;
#pragma unroll
            for (int i = 0; i < 6; i++) {
                int d4 = q8 * 6 + i;
                cpasync16(kd + d4 * 4, (d4 < 32) ? (const void*)(kn + d4) : (const void*)(kp + d4 - 32));
            }
#pragma unroll
            for (int i = 0; i < 4; i++) {
                int d4 = q8 * 4 + i;
                cpasync16(vd + d4 * 4, kn + 32 + d4);
            }
            CP_COMMIT();
        }

        if (k0 <= q0 + warp * 16 + 15) {
            const unsigned* Ks = Ksb[buf];
            const unsigned* Vs = Vsb[buf];

            // QK^T (32 keys = 4 nb blocks)
            float c[4][4];
#pragma unroll
            for (int nb = 0; nb < 4; nb++) {
#pragma unroll
                for (int e = 0; e < 4; e++) c[nb][e] = 0.f;
                const unsigned* krow = &Ks[(nb * 8 + g) * KS_STR];
#pragma unroll
                for (int kc = 0; kc < 24; kc++) {
                    unsigned bf[2] = {krow[kc * 8 + tg], krow[kc * 8 + tg + 4]};
                    mma_tf32(c[nb], aq[kc], bf);
                }
            }
            // scale in fp32
#pragma unroll
            for (int nb = 0; nb < 4; nb++)
#pragma unroll
                for (int e = 0; e < 4; e++) c[nb][e] *= scale;

            // causal mask (near-diagonal tiles only)
            if (k0 + FBN - 1 > q0 + warp * 16) {
                const int r0g = q0 + warp * 16 + g;
#pragma unroll
                for (int nb = 0; nb < 4; nb++) {
                    int col = k0 + nb * 8 + 2 * tg;
                    if (col     > r0g)     c[nb][0] = -3.0e38f;
                    if (col + 1 > r0g)     c[nb][1] = -3.0e38f;
                    if (col     > r0g + 8) c[nb][2] = -3.0e38f;
                    if (col + 1 > r0g + 8) c[nb][3] = -3.0e38f;
                }
            }

            // online softmax
            float tm0 = -3.0e38f, tm1 = -3.0e38f;
#pragma unroll
            for (int nb = 0; nb < 4; nb++) {
                tm0 = fmaxf(tm0, fmaxf(c[nb][0], c[nb][1]));
                tm1 = fmaxf(tm1, fmaxf(c[nb][2], c[nb][3]));
            }
            tm0 = fmaxf(tm0, __shfl_xor_sync(0xffffffffu, tm0, 1));
            tm0 = fmaxf(tm0, __shfl_xor_sync(0xffffffffu, tm0, 2));
            tm1 = fmaxf(tm1, __shfl_xor_sync(0xffffffffu, tm1, 1));
            tm1 = fmaxf(tm1, __shfl_xor_sync(0xffffffffu, tm1, 2));

            float nm0 = fmaxf(m0, tm0), nm1 = fmaxf(m1, tm1);
            float co0 = __expf(m0 - nm0), co1 = __expf(m1 - nm1);
            l0 *= co0; l1 *= co1;
#pragma unroll
            for (int nb = 0; nb < 16; nb++) {
                oacc[nb][0] *= co0; oacc[nb][1] *= co0;
                oacc[nb][2] *= co1; oacc[nb][3] *= co1;
            }
            m0 = nm0; m1 = nm1;

            unsigned* ps0 = &Ps[(size_t)(warp * 16 + g) * PS_STR];
            unsigned* ps1 = &Ps[(size_t)(warp * 16 + g + 8) * PS_STR];
            float ls0 = 0.f, ls1 = 0.f;
#pragma unroll
            for (int nb = 0; nb < 4; nb++) {
                float p0 = __expf(c[nb][0] - nm0);
                float p1 = __expf(c[nb][1] - nm0);
                float p2 = __expf(c[nb][2] - nm1);
                float p3 = __expf(c[nb][3] - nm1);
                ls0 += p0 + p1; ls1 += p2 + p3;
                ps0[nb * 8 + 2 * tg]     = f2tf32(p0);
                ps0[nb * 8 + 2 * tg + 1] = f2tf32(p1);
                ps1[nb * 8 + 2 * tg]     = f2tf32(p2);
                ps1[nb * 8 + 2 * tg + 1] = f2tf32(p3);
            }
            ls0 += __shfl_xor_sync(0xffffffffu, ls0, 1);
            ls0 += __shfl_xor_sync(0xffffffffu, ls0, 2);
            ls1 += __shfl_xor_sync(0xffffffffu, ls1, 1);
            ls1 += __shfl_xor_sync(0xffffffffu, ls1, 2);
            l0 += ls0; l1 += ls1;

            __syncwarp();

            // P @ V (k = 32 keys = 4 kc steps)
#pragma unroll
            for (int kc = 0; kc < 4; kc++) {
                unsigned ap[4] = {ps0[kc * 8 + tg], ps1[kc * 8 + tg],
                                  ps0[kc * 8 + tg + 4], ps1[kc * 8 + tg + 4]};
#pragma unroll
                for (int nb = 0; nb < 16; nb++) {
                    unsigned bv[2] = {Vs[(kc * 8 + tg) * VS_STR + nb * 8 + g],
                                      Vs[(kc * 8 + tg + 4) * VS_STR + nb * 8 + g]};
                    mma_tf32(oacc[nb], ap, bv);
                }
            }
            __syncwarp();
        }
    }

    // epilogue (tf32-rounded: feeds the final GEMM directly)
    float inv0 = 1.f / l0, inv1 = 1.f / l1;
    float* o0 = O + ((size_t)(b * SS + q0 + row0) * HH + h) * VD;
    float* o1 = o0 + (size_t)8 * HH * VD;
#pragma unroll
    for (int nb = 0; nb < 16; nb++) {
        *(float2*)(o0 + nb * 8 + 2 * tg) = make_float2(roundtf(oacc[nb][0] * inv0),
                                                       roundtf(oacc[nb][1] * inv0));
        *(float2*)(o1 + nb * 8 + 2 * tg) = make_float2(roundtf(oacc[nb][2] * inv1),
                                                       roundtf(oacc[nb][3] * inv1));
    }
}

// ---------------- host launcher ------------------------------------------
extern "C" void kernel_launch(void* const* d_in, const int* in_sizes, int n_in,
                              void* d_out, int out_size)
{
    const float* x         = (const float*)d_in[0];
    const float* w_dq      = (const float*)d_in[1];
    const float* q_a_norm  = (const float*)d_in[2];
    const float* w_uq      = (const float*)d_in[3];
    const float* w_dkv     = (const float*)d_in[4];
    const float* kv_a_norm = (const float*)d_in[5];
    const float* w_ukv     = (const float*)d_in[6];
    const float* w_o       = (const float*)d_in[7];
    float* out = (float*)d_out;

    float *cq, *q, *ckv, *kva, *kpe, *kv, *o, *ct, *st;
    float *xr, *wdq, *wuq, *wdkv, *wukv, *wo;
    cudaGetSymbolAddress((void**)&cq,  g_cq);
    cudaGetSymbolAddress((void**)&q,   g_q);
    cudaGetSymbolAddress((void**)&ckv, g_ckv);
    cudaGetSymbolAddress((void**)&kva, g_kva);
    cudaGetSymbolAddress((void**)&kpe, g_kpe);
    cudaGetSymbolAddress((void**)&kv,  g_kv);
    cudaGetSymbolAddress((void**)&o,   g_o);
    cudaGetSymbolAddress((void**)&ct,  g_cos);
    cudaGetSymbolAddress((void**)&st,  g_sin);
    cudaGetSymbolAddress((void**)&xr,   g_xr);
    cudaGetSymbolAddress((void**)&wdq,  g_wdq);
    cudaGetSymbolAddress((void**)&wuq,  g_wuq);
    cudaGetSymbolAddress((void**)&wdkv, g_wdkv);
    cudaGetSymbolAddress((void**)&wukv, g_wukv);
    cudaGetSymbolAddress((void**)&wo,   g_wo);

    cudaFuncSetAttribute(tgemm_k, cudaFuncAttributeMaxDynamicSharedMemorySize, TG_SMEM);
    cudaFuncSetAttribute(flash_k, cudaFuncAttributeMaxDynamicSharedMemorySize, FLASH_SMEM);

    rope_table_k<<<SS, 32>>>(ct, st);

    // pre-round GEMM operands to tf32
    cvt_k<<<592, 256>>>((const float4*)x,     (float4*)xr,   RTOT * DD / 4);
    cvt_k<<<592, 256>>>((const float4*)w_dq,  (float4*)wdq,  DD * Q_RANK / 4);
    cvt_k<<<592, 256>>>((const float4*)w_uq,  (float4*)wuq,  Q_RANK * HH * QH / 4);
    cvt_k<<<592, 256>>>((const float4*)w_dkv, (float4*)wdkv, DD * (KV_RANK + ROPE_D) / 4);
    cvt_k<<<592, 256>>>((const float4*)w_ukv, (float4*)wukv, KV_RANK * HH * KVH / 4);
    cvt_k<<<592, 256>>>((const float4*)w_o,   (float4*)wo,   HH * VD * DD / 4);

    // q path
    tgemm_k<<<dim3(Q_RANK / TBN, RTOT / TBM), 128, TG_SMEM>>>(xr, wdq, cq, RTOT, Q_RANK, DD);
    rmsnorm_k<<<RTOT, 256>>>(cq, cq, q_a_norm, Q_RANK, Q_RANK, Q_RANK);
    tgemm_k<<<dim3((HH * QH) / TBN, RTOT / TBM), 128, TG_SMEM>>>(cq, wuq, q, RTOT, HH * QH, Q_RANK);

    // kv path
    tgemm_k<<<dim3((KV_RANK + ROPE_D + TBN - 1) / TBN, RTOT / TBM), 128, TG_SMEM>>>(
        xr, wdkv, ckv, RTOT, KV_RANK + ROPE_D, DD);
    rmsnorm_k<<<RTOT, 256>>>(ckv, kva, kv_a_norm, KV_RANK, KV_RANK + ROPE_D, KV_RANK);
    tgemm_k<<<dim3((HH * KVH) / TBN, RTOT / TBM), 128, TG_SMEM>>>(kva, wukv, kv, RTOT, HH * KVH, KV_RANK);

    // RoPE
    rope_q_k<<<RTOT, dim3(32, HH)>>>(q, ct, st);
    rope_k_k<<<RTOT, 32>>>(ckv, kpe, ct, st);

    // pre-round flash operands so raw bits are tf32-exact
    cvt_k<<<592, 256>>>((const float4*)q,   (float4*)q,   RTOT * HH * QH / 4);
    cvt_k<<<592, 256>>>((const float4*)kv,  (float4*)kv,  RTOT * HH * KVH / 4);
    cvt_k<<<592, 256>>>((const float4*)kpe, (float4*)kpe, RTOT * ROPE_D / 4);

    // attention
    flash_k<<<dim3(SS / FBM, HH, BB), 256, FLASH_SMEM>>>(q, kv, kpe, o);

    // output projection
    tgemm_k<<<dim3(DD / TBN, RTOT / TBM), 128, TG_SMEM>>>(o, wo, out, RTOT, DD, HH * VD);
}

// round 12
// speedup vs baseline: 1.6231x; 1.6231x over previous
#include <cuda_runtime.h>
#include <cuda_fp16.h>
#include <math.h>
#include <stdint.h>

// Problem constants
#define BB 2
#define SS 2048
#define DD 2048
#define HH 16
#define NOPE 128
#define ROPE_D 64
#define VD 128
#define KV_RANK 512
#define Q_RANK 1536
#define QH (NOPE + ROPE_D)   // 192
#define KVH (NOPE + VD)      // 256
#define RTOT (BB * SS)       // 4096 rows

// ---------------- scratch (device globals, no allocation) ----------------
__device__ float g_cq [RTOT * Q_RANK];
__device__ float g_q  [RTOT * (HH * QH)];
__device__ float g_ckv[RTOT * (KV_RANK + ROPE_D)];
__device__ float g_kv [RTOT * (HH * KVH)];
__device__ float g_kpe[RTOT * ROPE_D];
__device__ float g_cos[SS * (ROPE_D / 2)];
__device__ float g_sin[SS * (ROPE_D / 2)];
// fp16 operand copies (weights TRANSPOSED: [N][K] K-major)
__device__ __half g_xh  [RTOT * DD];
__device__ __half g_wdqT [Q_RANK * DD];
__device__ __half g_wuqT [HH * QH * Q_RANK];
__device__ __half g_wdkvT[(KV_RANK + ROPE_D) * DD];
__device__ __half g_wukvT[HH * KVH * KV_RANK];
__device__ __half g_woT  [DD * HH * VD];
__device__ __half g_cqh [RTOT * Q_RANK];
__device__ __half g_kvah[RTOT * KV_RANK];
__device__ __half g_oh  [RTOT * (HH * VD)];

// ---------------- helpers -------------------------------------------------
__device__ __forceinline__ unsigned h2u(float a, float b) {
    __half2 h = __floats2half2_rn(a, b);
    return *(unsigned*)&h;
}

__device__ __forceinline__ void mma_f16(float c[4], const unsigned a[4], const unsigned b[2]) {
    asm volatile(
        "mma.sync.aligned.m16n8k16.row.col.f32.f16.f16.f32 "
        "{%0,%1,%2,%3}, {%4,%5,%6,%7}, {%8,%9}, {%0,%1,%2,%3};\n"
        : "+f"(c[0]), "+f"(c[1]), "+f"(c[2]), "+f"(c[3])
        : "r"(a[0]), "r"(a[1]), "r"(a[2]), "r"(a[3]), "r"(b[0]), "r"(b[1]));
}

__device__ __forceinline__ void ldmx2t(unsigned& b0, unsigned& b1, uint32_t a) {
    asm volatile("ldmatrix.sync.aligned.m8n8.x2.trans.shared.b16 {%0,%1}, [%2];"
                 : "=r"(b0), "=r"(b1) : "r"(a));
}

__device__ __forceinline__ void cpa16(uint32_t dst_smem, const void* src) {
    asm volatile("cp.async.cg.shared.global [%0], [%1], 16;\n" :: "r"(dst_smem), "l"(src));
}
#define CP_COMMIT() asm volatile("cp.async.commit_group;\n")
#define CP_WAIT(n)  asm volatile("cp.async.wait_group %0;\n" :: "n"(n))

__device__ __forceinline__ uint32_t smem_u32(const void* p) {
    uint32_t a;
    asm("{ .reg .u64 t; cvta.to.shared.u64 t, %1; cvt.u32.u64 %0, t; }" : "=r"(a) : "l"(p));
    return a;
}

// ---------------- fp32 -> fp16 linear convert -----------------------------
__global__ void cvth_k(const float4* __restrict__ in, __half* __restrict__ out, int n4)
{
    int i = blockIdx.x * blockDim.x + threadIdx.x;
    int stride = gridDim.x * blockDim.x;
    for (; i < n4; i += stride) {
        float4 v = in[i];
        uint2 w;
        w.x = h2u(v.x, v.y);
        w.y = h2u(v.z, v.w);
        *(uint2*)(out + (size_t)i * 4) = w;
    }
}

// ---------------- transpose + fp16: in[R][C] fp32 -> out[C][R] half -------
__global__ __launch_bounds__(256) void trth_k(const float* __restrict__ in,
                                              __half* __restrict__ out, int R, int C)
{
    __shared__ float tl[32][33];
    int c0 = blockIdx.x * 32, r0 = blockIdx.y * 32;
    int tx = threadIdx.x & 31, ty = threadIdx.x >> 5;   // 32 x 8
#pragma unroll
    for (int k = 0; k < 4; k++)
        tl[ty + 8 * k][tx] = in[(size_t)(r0 + ty + 8 * k) * C + c0 + tx];
    __syncthreads();
#pragma unroll
    for (int k = 0; k < 4; k++)
        out[(size_t)(c0 + ty + 8 * k) * R + r0 + tx] = __float2half(tl[tx][ty + 8 * k]);
}

// ---------------- fp16 tensor-core GEMM: C = A(MxK) @ Bt(NxK)^T -----------
// A [M][K] half row-major, Bt [N][K] half row-major (original B transposed).
// 128x128 CTA tile, BK=32 halves, 128 threads (4 warps, 64x64 warp tiles),
// double-buffered cp.async. M%128==0, K%32==0.
#define TBK 32
#define ASTR 40                       // halves; 20 words; conflict-free
#define HG_BUF (128 * ASTR)           // 5120 halves per buffer
#define HG_SMEM (4 * HG_BUF * 2)      // 40960 bytes

__global__ __launch_bounds__(128, 2) void hgemm_k(
    const __half* __restrict__ A, const __half* __restrict__ Bt,
    float* __restrict__ C, int M, int N, int K)
{
    extern __shared__ __half smh[];
    const uint32_t sb = smem_u32(smh);

    const int tid  = threadIdx.x;
    const int lane = tid & 31;
    const int warp = tid >> 5;
    const int wm = warp & 1;
    const int wn = warp >> 1;
    const int g  = lane >> 2;
    const int tg = lane & 3;
    const int n0 = blockIdx.x * 128;
    const int m0 = blockIdx.y * 128;

    float acc[4][8][4];
#pragma unroll
    for (int i = 0; i < 4; i++)
#pragma unroll
        for (int j = 0; j < 8; j++)
#pragma unroll
            for (int e = 0; e < 4; e++) acc[i][j][e] = 0.f;

    const int nt = K / TBK;

#define HG_LOAD(tt, bufi)                                                      \
    do {                                                                       \
        const int kb = (tt) * TBK;                                             \
        const uint32_t ao = (bufi) * (HG_BUF * 2);                             \
        const uint32_t bo = 2 * (HG_BUF * 2) + (bufi) * (HG_BUF * 2);          \
        _Pragma("unroll")                                                      \
        for (int s = 0; s < 4; s++) {                                          \
            int ch = tid + 128 * s; int row = ch >> 2, cc = ch & 3;            \
            cpa16(sb + ao + (row * ASTR + cc * 8) * 2,                         \
                  A + (size_t)(m0 + row) * K + kb + cc * 8);                   \
            int rc = n0 + row; if (rc > N - 1) rc = N - 1;                     \
            cpa16(sb + bo + (row * ASTR + cc * 8) * 2,                         \
                  Bt + (size_t)rc * K + kb + cc * 8);                          \
        }                                                                      \
        CP_COMMIT();                                                           \
    } while (0)

    HG_LOAD(0, 0);

    for (int t = 0; t < nt; t++) {
        const int buf = t & 1;
        if (t + 1 < nt) {
            HG_LOAD(t + 1, buf ^ 1);
            CP_WAIT(1);
        } else {
            CP_WAIT(0);
        }
        __syncthreads();

        const unsigned* Aw = (const unsigned*)smh + buf * (HG_BUF / 2);
        const unsigned* Bw = (const unsigned*)smh + HG_BUF + buf * (HG_BUF / 2);

#pragma unroll
        for (int kc = 0; kc < 2; kc++) {
            unsigned af[4][4], bf[8][2];
#pragma unroll
            for (int i = 0; i < 4; i++) {
                const int r = wm * 64 + i * 16 + g;
                const int base = r * 20 + kc * 8 + tg;
                af[i][0] = Aw[base];
                af[i][1] = Aw[base + 160];      // row +8
                af[i][2] = Aw[base + 4];        // k +8
                af[i][3] = Aw[base + 164];
            }
#pragma unroll
            for (int j = 0; j < 8; j++) {
                const int n = wn * 64 + j * 8 + g;
                const int base = n * 20 + kc * 8 + tg;
                bf[j][0] = Bw[base];
                bf[j][1] = Bw[base + 4];
            }
#pragma unroll
            for (int i = 0; i < 4; i++)
#pragma unroll
                for (int j = 0; j < 8; j++)
                    mma_f16(acc[i][j], af[i], bf[j]);
        }
        __syncthreads();
    }

#pragma unroll
    for (int i = 0; i < 4; i++) {
        const int r0 = m0 + wm * 64 + i * 16 + g;
#pragma unroll
        for (int j = 0; j < 8; j++) {
            const int c = n0 + wn * 64 + j * 8 + 2 * tg;
            if (c < N) {
                *(float2*)(C + (size_t)r0 * N + c) = make_float2(acc[i][j][0], acc[i][j][1]);
                *(float2*)(C + (size_t)(r0 + 8) * N + c) = make_float2(acc[i][j][2], acc[i][j][3]);
            }
        }
    }
}

// ---------------- RMSNorm (fp32 in -> fp16 out) ---------------------------
__global__ void rmsnorm_k(const float* in, __half* out, const float* __restrict__ w,
                          int cols, int in_stride, int out_stride)
{
    const int row = blockIdx.x;
    const float* xi = in + (size_t)row * in_stride;
    float s = 0.f;
    for (int c = threadIdx.x; c < cols; c += blockDim.x) {
        float v = xi[c];
        s += v * v;
    }
    __shared__ float red[8];
#pragma unroll
    for (int o = 16; o > 0; o >>= 1) s += __shfl_down_sync(0xffffffffu, s, o);
    int warp = threadIdx.x >> 5, lane = threadIdx.x & 31;
    if (lane == 0) red[warp] = s;
    __syncthreads();
    if (warp == 0) {
        s = (lane < (blockDim.x >> 5)) ? red[lane] : 0.f;
#pragma unroll
        for (int o = 4; o > 0; o >>= 1) s += __shfl_down_sync(0xffffffffu, s, o);
        if (lane == 0) red[0] = s;
    }
    __syncthreads();
    float r = rsqrtf(red[0] / (float)cols + 1e-6f);
    __half* yo = out + (size_t)row * out_stride;
    for (int c = threadIdx.x; c < cols; c += blockDim.x)
        yo[c] = __float2half(xi[c] * r * w[c]);
}

// ---------------- RoPE ---------------------------------------------------
__global__ void rope_table_k(float* ct, float* st)
{
    int s = blockIdx.x, i = threadIdx.x;
    double inv = exp(-((double)(2 * i) / 64.0) * log(10000.0));
    double ang = (double)s * inv;
    ct[s * 32 + i] = (float)cos(ang);
    st[s * 32 + i] = (float)sin(ang);
}

__global__ void rope_q_k(float* Q, const float* __restrict__ ct, const float* __restrict__ st)
{
    int bs = blockIdx.x;
    int s = bs & (SS - 1);
    int i = threadIdx.x;
    int h = threadIdx.y;
    size_t base = ((size_t)bs * HH + h) * QH + NOPE;
    float c = ct[s * 32 + i], sn = st[s * 32 + i];
    float x1 = Q[base + i], x2 = Q[base + 32 + i];
    Q[base + i]      = x1 * c - x2 * sn;
    Q[base + 32 + i] = x2 * c + x1 * sn;
}

__global__ void rope_k_k(const float* __restrict__ CKV, float* KPE,
                         const float* __restrict__ ct, const float* __restrict__ st)
{
    int bs = blockIdx.x;
    int s = bs & (SS - 1);
    int i = threadIdx.x;
    const float* src = CKV + (size_t)bs * (KV_RANK + ROPE_D) + KV_RANK;
    float c = ct[s * 32 + i], sn = st[s * 32 + i];
    float x1 = src[i], x2 = src[32 + i];
    KPE[(size_t)bs * ROPE_D + i]      = x1 * c - x2 * sn;
    KPE[(size_t)bs * ROPE_D + 32 + i] = x2 * c + x1 * sn;
}

// ---------------- fp16 tensor-core causal flash attention -----------------
// Block: (b, h, 128-query tile). 256 threads = 8 warps; warp w owns query
// rows q0 + 16w + {g, g+8}. Q persistent as fp16 A-frags. K/V converted to
// half in smem per 64-key tile. P stays in registers (QK C-frag -> PV A-frag
// layout identity). V B-frags via ldmatrix.x2.trans.
#define FBM 128
#define FBN 64
#define KSTR 200      // halves; 100 words (== 4 mod 32): conflict-free
#define VSTR 136      // halves; ldmatrix row stride 272B
#define FLASH_SMEM ((FBN * KSTR + FBN * VSTR) * 2)

__global__ __launch_bounds__(256) void flash_k(
    const float* __restrict__ Q, const float* __restrict__ KV,
    const float* __restrict__ KPE, __half* __restrict__ OH)
{
    extern __shared__ __half smf[];
    __half* Ks = smf;                      // [64][200]
    __half* Vs = smf + FBN * KSTR;         // [64][136]
    const uint32_t vb = smem_u32(Vs);

    const int q0 = blockIdx.x * FBM;
    const int h = blockIdx.y;
    const int b = blockIdx.z;
    const int t = threadIdx.x;
    const int warp = t >> 5;
    const int lane = t & 31;
    const int g = lane >> 2;
    const int tg = lane & 3;
    const int row0 = warp * 16 + g;
    const float scale = rsqrtf((float)QH);

    // persistent Q A-frags (fp16), scale pre-applied
    unsigned aq[12][4];
    {
        const float* qp0 = Q + ((size_t)(b * SS + q0 + row0) * HH + h) * QH;
        const float* qp1 = qp0 + (size_t)8 * HH * QH;
#pragma unroll
        for (int kc = 0; kc < 12; kc++) {
            const int d = kc * 16 + 2 * tg;
            aq[kc][0] = h2u(qp0[d] * scale,     qp0[d + 1] * scale);
            aq[kc][1] = h2u(qp1[d] * scale,     qp1[d + 1] * scale);
            aq[kc][2] = h2u(qp0[d + 8] * scale, qp0[d + 9] * scale);
            aq[kc][3] = h2u(qp1[d + 8] * scale, qp1[d + 9] * scale);
        }
    }

    float oacc[16][4];
#pragma unroll
    for (int i = 0; i < 16; i++)
#pragma unroll
        for (int e = 0; e < 4; e++) oacc[i][e] = 0.f;
    float m0 = -3.0e38f, m1 = -3.0e38f, l0 = 0.f, l1 = 0.f;

    const int lr = t >> 2;      // key row this thread loads (0..63)
    const int q4 = t & 3;

    for (int k0 = 0; k0 < q0 + FBM; k0 += FBN) {
        __syncthreads();
        // cooperative K/V load + fp32->fp16 convert (4 threads per key row)
        {
            const float4* kn = (const float4*)(KV + ((size_t)(b * SS + k0 + lr) * HH + h) * KVH);
            const float4* kp = (const float4*)(KPE + (size_t)(b * SS + k0 + lr) * ROPE_D);
#pragma unroll
            for (int i = 0; i < 12; i++) {
                int d4 = q4 * 12 + i;
                float4 v = (d4 < 32) ? kn[d4] : kp[d4 - 32];
                uint2 w; w.x = h2u(v.x, v.y); w.y = h2u(v.z, v.w);
                *(uint2*)(Ks + (size_t)lr * KSTR + d4 * 4) = w;
            }
#pragma unroll
            for (int i = 0; i < 8; i++) {
                int d4 = q4 * 8 + i;
                float4 v = kn[32 + d4];
                uint2 w; w.x = h2u(v.x, v.y); w.y = h2u(v.z, v.w);
                *(uint2*)(Vs + (size_t)lr * VSTR + d4 * 4) = w;
            }
        }
        __syncthreads();

        if (k0 > q0 + warp * 16 + 15) continue;   // fully masked for this warp

        // QK^T
        float c[8][4];
        const unsigned* Kw = (const unsigned*)Ks;
#pragma unroll
        for (int nb = 0; nb < 8; nb++) {
#pragma unroll
            for (int e = 0; e < 4; e++) c[nb][e] = 0.f;
            const unsigned* krow = Kw + (size_t)(nb * 8 + g) * (KSTR / 2);
#pragma unroll
            for (int kc = 0; kc < 12; kc++) {
                unsigned bf[2] = {krow[kc * 8 + tg], krow[kc * 8 + tg + 4]};
                mma_f16(c[nb], aq[kc], bf);
            }
        }

        // causal mask (near-diagonal tiles only)
        if (k0 + FBN - 1 > q0 + warp * 16) {
            const int r0g = q0 + warp * 16 + g;
#pragma unroll
            for (int nb = 0; nb < 8; nb++) {
                int col = k0 + nb * 8 + 2 * tg;
                if (col     > r0g)     c[nb][0] = -3.0e38f;
                if (col + 1 > r0g)     c[nb][1] = -3.0e38f;
                if (col     > r0g + 8) c[nb][2] = -3.0e38f;
                if (col + 1 > r0g + 8) c[nb][3] = -3.0e38f;
            }
        }

        // online softmax
        float tm0 = -3.0e38f, tm1 = -3.0e38f;
#pragma unroll
        for (int nb = 0; nb < 8; nb++) {
            tm0 = fmaxf(tm0, fmaxf(c[nb][0], c[nb][1]));
            tm1 = fmaxf(tm1, fmaxf(c[nb][2], c[nb][3]));
        }
        tm0 = fmaxf(tm0, __shfl_xor_sync(0xffffffffu, tm0, 1));
        tm0 = fmaxf(tm0, __shfl_xor_sync(0xffffffffu, tm0, 2));
        tm1 = fmaxf(tm1, __shfl_xor_sync(0xffffffffu, tm1, 1));
        tm1 = fmaxf(tm1, __shfl_xor_sync(0xffffffffu, tm1, 2));

        float nm0 = fmaxf(m0, tm0), nm1 = fmaxf(m1, tm1);
        float co0 = __expf(m0 - nm0), co1 = __expf(m1 - nm1);
        l0 *= co0; l1 *= co1;
#pragma unroll
        for (int nb = 0; nb < 16; nb++) {
            oacc[nb][0] *= co0; oacc[nb][1] *= co0;
            oacc[nb][2] *= co1; oacc[nb][3] *= co1;
        }
        m0 = nm0; m1 = nm1;

        // p = exp(scores) in place; accumulate row sums
        float ls0 = 0.f, ls1 = 0.f;
#pragma unroll
        for (int nb = 0; nb < 8; nb++) {
            c[nb][0] = __expf(c[nb][0] - nm0);
            c[nb][1] = __expf(c[nb][1] - nm0);
            c[nb][2] = __expf(c[nb][2] - nm1);
            c[nb][3] = __expf(c[nb][3] - nm1);
            ls0 += c[nb][0] + c[nb][1];
            ls1 += c[nb][2] + c[nb][3];
        }
        ls0 += __shfl_xor_sync(0xffffffffu, ls0, 1);
        ls0 += __shfl_xor_sync(0xffffffffu, ls0, 2);
        ls1 += __shfl_xor_sync(0xffffffffu, ls1, 1);
        ls1 += __shfl_xor_sync(0xffffffffu, ls1, 2);
        l0 += ls0; l1 += ls1;

        // P @ V: C-frag -> A-frag in registers; V B-frags via ldmatrix.trans
        const uint32_t vrow = vb + (uint32_t)(lane & 15) * (VSTR * 2);
#pragma unroll
        for (int kr = 0; kr < 4; kr++) {
            unsigned ap[4];
            ap[0] = h2u(c[2 * kr][0],     c[2 * kr][1]);
            ap[1] = h2u(c[2 * kr][2],     c[2 * kr][3]);
            ap[2] = h2u(c[2 * kr + 1][0], c[2 * kr + 1][1]);
            ap[3] = h2u(c[2 * kr + 1][2], c[2 * kr + 1][3]);
            const uint32_t kbase = vrow + (uint32_t)kr * 16 * (VSTR * 2);
#pragma unroll
            for (int nb = 0; nb < 16; nb++) {
                unsigned b0, b1;
                ldmx2t(b0, b1, kbase + nb * 16);
                unsigned bv[2] = {b0, b1};
                mma_f16(oacc[nb], ap, bv);
            }
        }
    }

    // epilogue: fp16 output (feeds the final GEMM)
    float inv0 = 1.f / l0, inv1 = 1.f / l1;
    __half* o0 = OH + ((size_t)(b * SS + q0 + row0) * HH + h) * VD;
    __half* o1 = o0 + (size_t)8 * HH * VD;
#pragma unroll
    for (int nb = 0; nb < 16; nb++) {
        *(unsigned*)(o0 + nb * 8 + 2 * tg) = h2u(oacc[nb][0] * inv0, oacc[nb][1] * inv0);
        *(unsigned*)(o1 + nb * 8 + 2 * tg) = h2u(oacc[nb][2] * inv1, oacc[nb][3] * inv1);
    }
}

// ---------------- host launcher ------------------------------------------
extern "C" void kernel_launch(void* const* d_in, const int* in_sizes, int n_in,
                              void* d_out, int out_size)
{
    const float* x         = (const float*)d_in[0];
    const float* w_dq      = (const float*)d_in[1];
    const float* q_a_norm  = (const float*)d_in[2];
    const float* w_uq      = (const float*)d_in[3];
    const float* w_dkv     = (const float*)d_in[4];
    const float* kv_a_norm = (const float*)d_in[5];
    const float* w_ukv     = (const float*)d_in[6];
    const float* w_o       = (const float*)d_in[7];
    float* out = (float*)d_out;

    float *cq, *q, *ckv, *kv, *kpe, *ct, *st;
    __half *xh, *wdqT, *wuqT, *wdkvT, *wukvT, *woT, *cqh, *kvah, *oh;
    cudaGetSymbolAddress((void**)&cq,  g_cq);
    cudaGetSymbolAddress((void**)&q,   g_q);
    cudaGetSymbolAddress((void**)&ckv, g_ckv);
    cudaGetSymbolAddress((void**)&kv,  g_kv);
    cudaGetSymbolAddress((void**)&kpe, g_kpe);
    cudaGetSymbolAddress((void**)&ct,  g_cos);
    cudaGetSymbolAddress((void**)&st,  g_sin);
    cudaGetSymbolAddress((void**)&xh,    g_xh);
    cudaGetSymbolAddress((void**)&wdqT,  g_wdqT);
    cudaGetSymbolAddress((void**)&wuqT,  g_wuqT);
    cudaGetSymbolAddress((void**)&wdkvT, g_wdkvT);
    cudaGetSymbolAddress((void**)&wukvT, g_wukvT);
    cudaGetSymbolAddress((void**)&woT,   g_woT);
    cudaGetSymbolAddress((void**)&cqh,   g_cqh);
    cudaGetSymbolAddress((void**)&kvah,  g_kvah);
    cudaGetSymbolAddress((void**)&oh,    g_oh);

    cudaFuncSetAttribute(hgemm_k, cudaFuncAttributeMaxDynamicSharedMemorySize, HG_SMEM);
    cudaFuncSetAttribute(flash_k, cudaFuncAttributeMaxDynamicSharedMemorySize, FLASH_SMEM);

    rope_table_k<<<SS, 32>>>(ct, st);

    // convert A operand; transpose+convert weights to [N][K] half
    cvth_k<<<592, 256>>>((const float4*)x, xh, RTOT * DD / 4);
    trth_k<<<dim3(Q_RANK / 32, DD / 32), 256>>>(w_dq, wdqT, DD, Q_RANK);
    trth_k<<<dim3((HH * QH) / 32, Q_RANK / 32), 256>>>(w_uq, wuqT, Q_RANK, HH * QH);
    trth_k<<<dim3((KV_RANK + ROPE_D) / 32, DD / 32), 256>>>(w_dkv, wdkvT, DD, KV_RANK + ROPE_D);
    trth_k<<<dim3((HH * KVH) / 32, KV_RANK / 32), 256>>>(w_ukv, wukvT, KV_RANK, HH * KVH);
    trth_k<<<dim3(DD / 32, (HH * VD) / 32), 256>>>(w_o, woT, HH * VD, DD);

    // q path
    hgemm_k<<<dim3(Q_RANK / 128, RTOT / 128), 128, HG_SMEM>>>(xh, wdqT, cq, RTOT, Q_RANK, DD);
    rmsnorm_k<<<RTOT, 256>>>(cq, cqh, q_a_norm, Q_RANK, Q_RANK, Q_RANK);
    hgemm_k<<<dim3((HH * QH) / 128, RTOT / 128), 128, HG_SMEM>>>(cqh, wuqT, q, RTOT, HH * QH, Q_RANK);

    // kv path
    hgemm_k<<<dim3((KV_RANK + ROPE_D + 127) / 128, RTOT / 128), 128, HG_SMEM>>>(
        xh, wdkvT, ckv, RTOT, KV_RANK + ROPE_D, DD);
    rmsnorm_k<<<RTOT, 256>>>(ckv, kvah, kv_a_norm, KV_RANK, KV_RANK + ROPE_D, KV_RANK);
    hgemm_k<<<dim3((HH * KVH) / 128, RTOT / 128), 128, HG_SMEM>>>(kvah, wukvT, kv, RTOT, HH * KVH, KV_RANK);

    // RoPE
    rope_q_k<<<RTOT, dim3(32, HH)>>>(q, ct, st);
    rope_k_k<<<RTOT, 32>>>(ckv, kpe, ct, st);

    // attention (fp16 MMA, fp32 softmax/accum) -> fp16 output
    flash_k<<<dim3(SS / FBM, HH, BB), 256, FLASH_SMEM>>>(q, kv, kpe, oh);

    // output projection
    hgemm_k<<<dim3(DD / 128, RTOT / 128), 128, HG_SMEM>>>(oh, woT, out, RTOT, DD, HH * VD);
}

// round 13
// speedup vs baseline: 2.0263x; 1.2484x over previous
#include <cuda_runtime.h>
#include <cuda_fp16.h>
#include <math.h>
#include <stdint.h>

// Problem constants
#define BB 2
#define SS 2048
#define DD 2048
#define HH 16
#define NOPE 128
#define ROPE_D 64
#define VD 128
#define KV_RANK 512
#define Q_RANK 1536
#define QH (NOPE + ROPE_D)   // 192
#define KVH (NOPE + VD)      // 256
#define RTOT (BB * SS)       // 4096 rows

// ---------------- scratch (device globals, no allocation) ----------------
__device__ float g_cq [RTOT * Q_RANK];
__device__ float g_q  [RTOT * (HH * QH)];
__device__ float g_ckv[RTOT * (KV_RANK + ROPE_D)];
__device__ float g_kv [RTOT * (HH * KVH)];
__device__ float g_kpe[RTOT * ROPE_D];
__device__ float g_cos[SS * (ROPE_D / 2)];
__device__ float g_sin[SS * (ROPE_D / 2)];
// fp16 operand copies (weights TRANSPOSED: [N][K] K-major)
__device__ __half g_xh  [RTOT * DD];
__device__ __half g_wdqT [Q_RANK * DD];
__device__ __half g_wuqT [HH * QH * Q_RANK];
__device__ __half g_wdkvT[(KV_RANK + ROPE_D) * DD];
__device__ __half g_wukvT[HH * KVH * KV_RANK];
__device__ __half g_woT  [DD * HH * VD];
__device__ __half g_cqh [RTOT * Q_RANK];
__device__ __half g_kvah[RTOT * KV_RANK];
__device__ __half g_oh  [RTOT * (HH * VD)];
__device__ __half g_qh  [RTOT * (HH * QH)];
__device__ __half g_kvh [RTOT * (HH * KVH)];
__device__ __half g_kpeh[RTOT * ROPE_D];

// ---------------- helpers -------------------------------------------------
__device__ __forceinline__ unsigned h2u(float a, float b) {
    __half2 h = __floats2half2_rn(a, b);
    return *(unsigned*)&h;
}

__device__ __forceinline__ void mma_f16(float c[4], const unsigned a[4], const unsigned b[2]) {
    asm volatile(
        "mma.sync.aligned.m16n8k16.row.col.f32.f16.f16.f32 "
        "{%0,%1,%2,%3}, {%4,%5,%6,%7}, {%8,%9}, {%0,%1,%2,%3};\n"
        : "+f"(c[0]), "+f"(c[1]), "+f"(c[2]), "+f"(c[3])
        : "r"(a[0]), "r"(a[1]), "r"(a[2]), "r"(a[3]), "r"(b[0]), "r"(b[1]));
}

__device__ __forceinline__ void ldmx2t(unsigned& b0, unsigned& b1, uint32_t a) {
    asm volatile("ldmatrix.sync.aligned.m8n8.x2.trans.shared.b16 {%0,%1}, [%2];"
                 : "=r"(b0), "=r"(b1) : "r"(a));
}
__device__ __forceinline__ void ldmx4(unsigned& d0, unsigned& d1, unsigned& d2,
                                      unsigned& d3, uint32_t a) {
    asm volatile("ldmatrix.sync.aligned.m8n8.x4.shared.b16 {%0,%1,%2,%3}, [%4];"
                 : "=r"(d0), "=r"(d1), "=r"(d2), "=r"(d3) : "r"(a));
}

__device__ __forceinline__ void cpa16(uint32_t dst_smem, const void* src) {
    asm volatile("cp.async.cg.shared.global [%0], [%1], 16;\n" :: "r"(dst_smem), "l"(src));
}
#define CP_COMMIT() asm volatile("cp.async.commit_group;\n")
#define CP_WAIT(n)  asm volatile("cp.async.wait_group %0;\n" :: "n"(n))

__device__ __forceinline__ uint32_t smem_u32(const void* p) {
    uint32_t a;
    asm("{ .reg .u64 t; cvta.to.shared.u64 t, %1; cvt.u32.u64 %0, t; }" : "=r"(a) : "l"(p));
    return a;
}

// ---------------- fp32 -> fp16 linear convert -----------------------------
__global__ void cvth_k(const float4* __restrict__ in, __half* __restrict__ out, int n4)
{
    int i = blockIdx.x * blockDim.x + threadIdx.x;
    int stride = gridDim.x * blockDim.x;
    for (; i < n4; i += stride) {
        float4 v = in[i];
        uint2 w;
        w.x = h2u(v.x, v.y);
        w.y = h2u(v.z, v.w);
        *(uint2*)(out + (size_t)i * 4) = w;
    }
}

// ---------------- transpose + fp16: in[R][C] fp32 -> out[C][R] half -------
__global__ __launch_bounds__(256) void trth_k(const float* __restrict__ in,
                                              __half* __restrict__ out, int R, int C)
{
    __shared__ float tl[32][33];
    int c0 = blockIdx.x * 32, r0 = blockIdx.y * 32;
    int tx = threadIdx.x & 31, ty = threadIdx.x >> 5;   // 32 x 8
#pragma unroll
    for (int k = 0; k < 4; k++)
        tl[ty + 8 * k][tx] = in[(size_t)(r0 + ty + 8 * k) * C + c0 + tx];
    __syncthreads();
#pragma unroll
    for (int k = 0; k < 4; k++)
        out[(size_t)(c0 + ty + 8 * k) * R + r0 + tx] = __float2half(tl[tx][ty + 8 * k]);
}

// ---------------- fp16 tensor-core GEMM: C = A(MxK) @ Bt(NxK)^T -----------
// ldmatrix fragment loads. 128x128 CTA tile, BK=32 halves, 128 threads
// (4 warps, 64x64 warp tiles), double-buffered cp.async. M%128==0, K%32==0.
#define TBK 32
#define ASTR 40                       // halves; 80B row stride, conflict-free
#define HG_BUF (128 * ASTR)           // halves per buffer
#define HG_SMEM (4 * HG_BUF * 2)      // 40960 bytes

__global__ __launch_bounds__(128, 2) void hgemm_k(
    const __half* __restrict__ A, const __half* __restrict__ Bt,
    float* __restrict__ C, int M, int N, int K)
{
    extern __shared__ __half smh[];
    const uint32_t sb = smem_u32(smh);

    const int tid  = threadIdx.x;
    const int lane = tid & 31;
    const int warp = tid >> 5;
    const int wm = warp & 1;
    const int wn = warp >> 1;
    const int g  = lane >> 2;
    const int tg = lane & 3;
    const int n0 = blockIdx.x * 128;
    const int m0 = blockIdx.y * 128;

    // ldmatrix lane addressing
    const int lm = lane >> 3, lr8 = lane & 7;
    const int aRowOff = (lm & 1) * 8 + lr8;     // A: row within 16-row block
    const int aKOff   = (lm >> 1) * 8;          // A: k within 16
    const int bRowOff = (lm >> 1) * 8 + lr8;    // B: n within 16-row block
    const int bKOff   = (lm & 1) * 8;           // B: k within 16

    float acc[4][8][4];
#pragma unroll
    for (int i = 0; i < 4; i++)
#pragma unroll
        for (int j = 0; j < 8; j++)
#pragma unroll
            for (int e = 0; e < 4; e++) acc[i][j][e] = 0.f;

    const int nt = K / TBK;

#define HG_LOAD(tt, bufi)                                                      \
    do {                                                                       \
        const int kb = (tt) * TBK;                                             \
        const uint32_t ao = (bufi) * (HG_BUF * 2);                             \
        const uint32_t bo = 2 * (HG_BUF * 2) + (bufi) * (HG_BUF * 2);          \
        _Pragma("unroll")                                                      \
        for (int s = 0; s < 4; s++) {                                          \
            int ch = tid + 128 * s; int row = ch >> 2, cc = ch & 3;            \
            cpa16(sb + ao + (row * ASTR + cc * 8) * 2,                         \
                  A + (size_t)(m0 + row) * K + kb + cc * 8);                   \
            int rc = n0 + row; if (rc > N - 1) rc = N - 1;                     \
            cpa16(sb + bo + (row * ASTR + cc * 8) * 2,                         \
                  Bt + (size_t)rc * K + kb + cc * 8);                          \
        }                                                                      \
        CP_COMMIT();                                                           \
    } while (0)

    HG_LOAD(0, 0);

    for (int t = 0; t < nt; t++) {
        const int buf = t & 1;
        if (t + 1 < nt) {
            HG_LOAD(t + 1, buf ^ 1);
            CP_WAIT(1);
        } else {
            CP_WAIT(0);
        }
        __syncthreads();

        const uint32_t abase = sb + buf * (HG_BUF * 2);
        const uint32_t bbase = sb + 2 * (HG_BUF * 2) + buf * (HG_BUF * 2);

#pragma unroll
        for (int kc = 0; kc < 2; kc++) {
            unsigned af[4][4], bf[8][2];
#pragma unroll
            for (int i = 0; i < 4; i++) {
                uint32_t a = abase + (uint32_t)(((wm * 64 + i * 16 + aRowOff) * ASTR
                                                + kc * 16 + aKOff) * 2);
                ldmx4(af[i][0], af[i][1], af[i][2], af[i][3], a);
            }
#pragma unroll
            for (int jj = 0; jj < 4; jj++) {
                uint32_t a = bbase + (uint32_t)(((wn * 64 + jj * 16 + bRowOff) * ASTR
                                                + kc * 16 + bKOff) * 2);
                ldmx4(bf[2 * jj][0], bf[2 * jj][1], bf[2 * jj + 1][0], bf[2 * jj + 1][1], a);
            }
#pragma unroll
            for (int i = 0; i < 4; i++)
#pragma unroll
                for (int j = 0; j < 8; j++)
                    mma_f16(acc[i][j], af[i], bf[j]);
        }
        __syncthreads();
    }

#pragma unroll
    for (int i = 0; i < 4; i++) {
        const int r0 = m0 + wm * 64 + i * 16 + g;
#pragma unroll
        for (int j = 0; j < 8; j++) {
            const int c = n0 + wn * 64 + j * 8 + 2 * tg;
            if (c < N) {
                *(float2*)(C + (size_t)r0 * N + c) = make_float2(acc[i][j][0], acc[i][j][1]);
                *(float2*)(C + (size_t)(r0 + 8) * N + c) = make_float2(acc[i][j][2], acc[i][j][3]);
            }
        }
    }
}

// ---------------- RMSNorm (fp32 in -> fp16 out) ---------------------------
__global__ void rmsnorm_k(const float* in, __half* out, const float* __restrict__ w,
                          int cols, int in_stride, int out_stride)
{
    const int row = blockIdx.x;
    const float* xi = in + (size_t)row * in_stride;
    float s = 0.f;
    for (int c = threadIdx.x; c < cols; c += blockDim.x) {
        float v = xi[c];
        s += v * v;
    }
    __shared__ float red[8];
#pragma unroll
    for (int o = 16; o > 0; o >>= 1) s += __shfl_down_sync(0xffffffffu, s, o);
    int warp = threadIdx.x >> 5, lane = threadIdx.x & 31;
    if (lane == 0) red[warp] = s;
    __syncthreads();
    if (warp == 0) {
        s = (lane < (blockDim.x >> 5)) ? red[lane] : 0.f;
#pragma unroll
        for (int o = 4; o > 0; o >>= 1) s += __shfl_down_sync(0xffffffffu, s, o);
        if (lane == 0) red[0] = s;
    }
    __syncthreads();
    float r = rsqrtf(red[0] / (float)cols + 1e-6f);
    __half* yo = out + (size_t)row * out_stride;
    for (int c = threadIdx.x; c < cols; c += blockDim.x)
        yo[c] = __float2half(xi[c] * r * w[c]);
}

// ---------------- RoPE ---------------------------------------------------
__global__ void rope_table_k(float* ct, float* st)
{
    int s = blockIdx.x, i = threadIdx.x;
    double inv = exp(-((double)(2 * i) / 64.0) * log(10000.0));
    double ang = (double)s * inv;
    ct[s * 32 + i] = (float)cos(ang);
    st[s * 32 + i] = (float)sin(ang);
}

__global__ void rope_q_k(float* Q, const float* __restrict__ ct, const float* __restrict__ st)
{
    int bs = blockIdx.x;
    int s = bs & (SS - 1);
    int i = threadIdx.x;
    int h = threadIdx.y;
    size_t base = ((size_t)bs * HH + h) * QH + NOPE;
    float c = ct[s * 32 + i], sn = st[s * 32 + i];
    float x1 = Q[base + i], x2 = Q[base + 32 + i];
    Q[base + i]      = x1 * c - x2 * sn;
    Q[base + 32 + i] = x2 * c + x1 * sn;
}

__global__ void rope_k_k(const float* __restrict__ CKV, float* KPE,
                         const float* __restrict__ ct, const float* __restrict__ st)
{
    int bs = blockIdx.x;
    int s = bs & (SS - 1);
    int i = threadIdx.x;
    const float* src = CKV + (size_t)bs * (KV_RANK + ROPE_D) + KV_RANK;
    float c = ct[s * 32 + i], sn = st[s * 32 + i];
    float x1 = src[i], x2 = src[32 + i];
    KPE[(size_t)bs * ROPE_D + i]      = x1 * c - x2 * sn;
    KPE[(size_t)bs * ROPE_D + 32 + i] = x2 * c + x1 * sn;
}

// ---------------- fp16 tensor-core causal flash attention -----------------
// 256 threads = 8 warps; warp w owns query rows q0 + 16w + {g, g+8}.
// All operands pre-converted fp16 in global. K/V staged by double-buffered
// cp.async 64-key tiles. Scale applied post-MMA in fp32. P stays in regs.
#define FBM 128
#define FBN 64
#define KSTR 200      // halves; 400B rows, 16B-granular, conflict-free LDS
#define VSTR 136      // halves; 272B rows
#define KELE (FBN * KSTR)
#define VELE (FBN * VSTR)
#define FLASH_SMEM (2 * (KELE + VELE) * 2)

__global__ __launch_bounds__(256) void flash_k(
    const __half* __restrict__ QH_g, const __half* __restrict__ KVH_g,
    const __half* __restrict__ KPEH_g, __half* __restrict__ OH)
{
    extern __shared__ __half smf[];
    const uint32_t sbase = smem_u32(smf);

    const int q0 = blockIdx.x * FBM;
    const int h = blockIdx.y;
    const int b = blockIdx.z;
    const int t = threadIdx.x;
    const int warp = t >> 5;
    const int lane = t & 31;
    const int g = lane >> 2;
    const int tg = lane & 3;
    const int row0 = warp * 16 + g;
    const float scale = rsqrtf((float)QH);

    // persistent Q A-frags (fp16, unscaled)
    unsigned aq[12][4];
    {
        const unsigned* qp0 = (const unsigned*)(QH_g + ((size_t)(b * SS + q0 + row0) * HH + h) * QH);
        const unsigned* qp1 = qp0 + (size_t)8 * HH * QH / 2;
#pragma unroll
        for (int kc = 0; kc < 12; kc++) {
            aq[kc][0] = qp0[kc * 8 + tg];
            aq[kc][1] = qp1[kc * 8 + tg];
            aq[kc][2] = qp0[kc * 8 + tg + 4];
            aq[kc][3] = qp1[kc * 8 + tg + 4];
        }
    }

    float oacc[16][4];
#pragma unroll
    for (int i = 0; i < 16; i++)
#pragma unroll
        for (int e = 0; e < 4; e++) oacc[i][e] = 0.f;
    float m0 = -3.0e38f, m1 = -3.0e38f, l0 = 0.f, l1 = 0.f;

    // cp.async loader: 4 threads per key row
    const int flr = t >> 2;
    const int q4 = t & 3;
    const int ntiles = (q0 + FBM) / FBN;

#define FL_LOAD(tt, bufi)                                                          \
    do {                                                                           \
        const int kk0 = (tt) * FBN;                                                \
        const __half* kvrow = KVH_g + ((size_t)(b * SS + kk0 + flr) * HH + h) * KVH;\
        const __half* kprow = KPEH_g + (size_t)(b * SS + kk0 + flr) * ROPE_D;      \
        const uint32_t kdst = sbase + (bufi) * (KELE * 2) + flr * (KSTR * 2);      \
        const uint32_t vdst = sbase + 2 * (KELE * 2) + (bufi) * (VELE * 2)         \
                              + flr * (VSTR * 2);                                  \
        _Pragma("unroll")                                                          \
        for (int i = 0; i < 6; i++) {                                              \
            int c = q4 * 6 + i;                                                    \
            const __half* src = (c < 16) ? kvrow + c * 8 : kprow + (c - 16) * 8;   \
            cpa16(kdst + c * 16, src);                                             \
        }                                                                          \
        _Pragma("unroll")                                                          \
        for (int i = 0; i < 4; i++) {                                              \
            int c = q4 * 4 + i;                                                    \
            cpa16(vdst + c * 16, kvrow + 128 + c * 8);                             \
        }                                                                          \
        CP_COMMIT();                                                               \
    } while (0)

    FL_LOAD(0, 0);

    for (int tile = 0; tile < ntiles; tile++) {
        const int k0 = tile * FBN;
        const int buf = tile & 1;
        if (tile + 1 < ntiles) {
            FL_LOAD(tile + 1, buf ^ 1);
            CP_WAIT(1);
        } else {
            CP_WAIT(0);
        }
        __syncthreads();

        if (k0 <= q0 + warp * 16 + 15) {   // not fully masked for this warp
            const unsigned* Kw = (const unsigned*)smf + buf * (KELE / 2);
            const uint32_t vb = sbase + 2 * (KELE * 2) + buf * (VELE * 2);

            // QK^T
            float c[8][4];
#pragma unroll
            for (int nb = 0; nb < 8; nb++) {
#pragma unroll
                for (int e = 0; e < 4; e++) c[nb][e] = 0.f;
                const unsigned* krow = Kw + (size_t)(nb * 8 + g) * (KSTR / 2);
#pragma unroll
                for (int kc = 0; kc < 12; kc++) {
                    unsigned bfr[2] = {krow[kc * 8 + tg], krow[kc * 8 + tg + 4]};
                    mma_f16(c[nb], aq[kc], bfr);
                }
            }
            // scale in fp32
#pragma unroll
            for (int nb = 0; nb < 8; nb++)
#pragma unroll
                for (int e = 0; e < 4; e++) c[nb][e] *= scale;

            // causal mask (near-diagonal tiles only)
            if (k0 + FBN - 1 > q0 + warp * 16) {
                const int r0g = q0 + warp * 16 + g;
#pragma unroll
                for (int nb = 0; nb < 8; nb++) {
                    int col = k0 + nb * 8 + 2 * tg;
                    if (col     > r0g)     c[nb][0] = -3.0e38f;
                    if (col + 1 > r0g)     c[nb][1] = -3.0e38f;
                    if (col     > r0g + 8) c[nb][2] = -3.0e38f;
                    if (col + 1 > r0g + 8) c[nb][3] = -3.0e38f;
                }
            }

            // online softmax
            float tm0 = -3.0e38f, tm1 = -3.0e38f;
#pragma unroll
            for (int nb = 0; nb < 8; nb++) {
                tm0 = fmaxf(tm0, fmaxf(c[nb][0], c[nb][1]));
                tm1 = fmaxf(tm1, fmaxf(c[nb][2], c[nb][3]));
            }
            tm0 = fmaxf(tm0, __shfl_xor_sync(0xffffffffu, tm0, 1));
            tm0 = fmaxf(tm0, __shfl_xor_sync(0xffffffffu, tm0, 2));
            tm1 = fmaxf(tm1, __shfl_xor_sync(0xffffffffu, tm1, 1));
            tm1 = fmaxf(tm1, __shfl_xor_sync(0xffffffffu, tm1, 2));

            float nm0 = fmaxf(m0, tm0), nm1 = fmaxf(m1, tm1);
            float co0 = __expf(m0 - nm0), co1 = __expf(m1 - nm1);
            l0 *= co0; l1 *= co1;
#pragma unroll
            for (int nb = 0; nb < 16; nb++) {
                oacc[nb][0] *= co0; oacc[nb][1] *= co0;
                oacc[nb][2] *= co1; oacc[nb][3] *= co1;
            }
            m0 = nm0; m1 = nm1;

            float ls0 = 0.f, ls1 = 0.f;
#pragma unroll
            for (int nb = 0; nb < 8; nb++) {
                c[nb][0] = __expf(c[nb][0] - nm0);
                c[nb][1] = __expf(c[nb][1] - nm0);
                c[nb][2] = __expf(c[nb][2] - nm1);
                c[nb][3] = __expf(c[nb][3] - nm1);
                ls0 += c[nb][0] + c[nb][1];
                ls1 += c[nb][2] + c[nb][3];
            }
            ls0 += __shfl_xor_sync(0xffffffffu, ls0, 1);
            ls0 += __shfl_xor_sync(0xffffffffu, ls0, 2);
            ls1 += __shfl_xor_sync(0xffffffffu, ls1, 1);
            ls1 += __shfl_xor_sync(0xffffffffu, ls1, 2);
            l0 += ls0; l1 += ls1;

            // P @ V (C-frag -> A-frag in regs; V B-frags via ldmatrix.trans)
            const uint32_t vrow = vb + (uint32_t)(lane & 15) * (VSTR * 2);
#pragma unroll
            for (int kr = 0; kr < 4; kr++) {
                unsigned ap[4];
                ap[0] = h2u(c[2 * kr][0],     c[2 * kr][1]);
                ap[1] = h2u(c[2 * kr][2],     c[2 * kr][3]);
                ap[2] = h2u(c[2 * kr + 1][0], c[2 * kr + 1][1]);
                ap[3] = h2u(c[2 * kr + 1][2], c[2 * kr + 1][3]);
                const uint32_t kbase = vrow + (uint32_t)kr * 16 * (VSTR * 2);
#pragma unroll
                for (int nb = 0; nb < 16; nb++) {
                    unsigned b0, b1;
                    ldmx2t(b0, b1, kbase + nb * 16);
                    unsigned bv[2] = {b0, b1};
                    mma_f16(oacc[nb], ap, bv);
                }
            }
        }
        __syncthreads();
    }

    // epilogue: fp16 output (feeds the final GEMM)
    float inv0 = 1.f / l0, inv1 = 1.f / l1;
    __half* o0 = OH + ((size_t)(b * SS + q0 + row0) * HH + h) * VD;
    __half* o1 = o0 + (size_t)8 * HH * VD;
#pragma unroll
    for (int nb = 0; nb < 16; nb++) {
        *(unsigned*)(o0 + nb * 8 + 2 * tg) = h2u(oacc[nb][0] * inv0, oacc[nb][1] * inv0);
        *(unsigned*)(o1 + nb * 8 + 2 * tg) = h2u(oacc[nb][2] * inv1, oacc[nb][3] * inv1);
    }
}

// ---------------- host launcher ------------------------------------------
extern "C" void kernel_launch(void* const* d_in, const int* in_sizes, int n_in,
                              void* d_out, int out_size)
{
    const float* x         = (const float*)d_in[0];
    const float* w_dq      = (const float*)d_in[1];
    const float* q_a_norm  = (const float*)d_in[2];
    const float* w_uq      = (const float*)d_in[3];
    const float* w_dkv     = (const float*)d_in[4];
    const float* kv_a_norm = (const float*)d_in[5];
    const float* w_ukv     = (const float*)d_in[6];
    const float* w_o       = (const float*)d_in[7];
    float* out = (float*)d_out;

    float *cq, *q, *ckv, *kv, *kpe, *ct, *st;
    __half *xh, *wdqT, *wuqT, *wdkvT, *wukvT, *woT, *cqh, *kvah, *oh, *qh, *kvh, *kpeh;
    cudaGetSymbolAddress((void**)&cq,  g_cq);
    cudaGetSymbolAddress((void**)&q,   g_q);
    cudaGetSymbolAddress((void**)&ckv, g_ckv);
    cudaGetSymbolAddress((void**)&kv,  g_kv);
    cudaGetSymbolAddress((void**)&kpe, g_kpe);
    cudaGetSymbolAddress((void**)&ct,  g_cos);
    cudaGetSymbolAddress((void**)&st,  g_sin);
    cudaGetSymbolAddress((void**)&xh,    g_xh);
    cudaGetSymbolAddress((void**)&wdqT,  g_wdqT);
    cudaGetSymbolAddress((void**)&wuqT,  g_wuqT);
    cudaGetSymbolAddress((void**)&wdkvT, g_wdkvT);
    cudaGetSymbolAddress((void**)&wukvT, g_wukvT);
    cudaGetSymbolAddress((void**)&woT,   g_woT);
    cudaGetSymbolAddress((void**)&cqh,   g_cqh);
    cudaGetSymbolAddress((void**)&kvah,  g_kvah);
    cudaGetSymbolAddress((void**)&oh,    g_oh);
    cudaGetSymbolAddress((void**)&qh,    g_qh);
    cudaGetSymbolAddress((void**)&kvh,   g_kvh);
    cudaGetSymbolAddress((void**)&kpeh,  g_kpeh);

    cudaFuncSetAttribute(hgemm_k, cudaFuncAttributeMaxDynamicSharedMemorySize, HG_SMEM);
    cudaFuncSetAttribute(flash_k, cudaFuncAttributeMaxDynamicSharedMemorySize, FLASH_SMEM);

    rope_table_k<<<SS, 32>>>(ct, st);

    // convert A operand; transpose+convert weights to [N][K] half
    cvth_k<<<592, 256>>>((const float4*)x, xh, RTOT * DD / 4);
    trth_k<<<dim3(Q_RANK / 32, DD / 32), 256>>>(w_dq, wdqT, DD, Q_RANK);
    trth_k<<<dim3((HH * QH) / 32, Q_RANK / 32), 256>>>(w_uq, wuqT, Q_RANK, HH * QH);
    trth_k<<<dim3((KV_RANK + ROPE_D) / 32, DD / 32), 256>>>(w_dkv, wdkvT, DD, KV_RANK + ROPE_D);
    trth_k<<<dim3((HH * KVH) / 32, KV_RANK / 32), 256>>>(w_ukv, wukvT, KV_RANK, HH * KVH);
    trth_k<<<dim3(DD / 32, (HH * VD) / 32), 256>>>(w_o, woT, HH * VD, DD);

    // q path
    hgemm_k<<<dim3(Q_RANK / 128, RTOT / 128), 128, HG_SMEM>>>(xh, wdqT, cq, RTOT, Q_RANK, DD);
    rmsnorm_k<<<RTOT, 256>>>(cq, cqh, q_a_norm, Q_RANK, Q_RANK, Q_RANK);
    hgemm_k<<<dim3((HH * QH) / 128, RTOT / 128), 128, HG_SMEM>>>(cqh, wuqT, q, RTOT, HH * QH, Q_RANK);

    // kv path
    hgemm_k<<<dim3((KV_RANK + ROPE_D + 127) / 128, RTOT / 128), 128, HG_SMEM>>>(
        xh, wdkvT, ckv, RTOT, KV_RANK + ROPE_D, DD);
    rmsnorm_k<<<RTOT, 256>>>(ckv, kvah, kv_a_norm, KV_RANK, KV_RANK + ROPE_D, KV_RANK);
    hgemm_k<<<dim3((HH * KVH) / 128, RTOT / 128), 128, HG_SMEM>>>(kvah, wukvT, kv, RTOT, HH * KVH, KV_RANK);

    // RoPE (fp32), then convert flash operands to fp16
    rope_q_k<<<RTOT, dim3(32, HH)>>>(q, ct, st);
    rope_k_k<<<RTOT, 32>>>(ckv, kpe, ct, st);
    cvth_k<<<592, 256>>>((const float4*)q,   qh,   RTOT * HH * QH / 4);
    cvth_k<<<592, 256>>>((const float4*)kv,  kvh,  RTOT * HH * KVH / 4);
    cvth_k<<<592, 256>>>((const float4*)kpe, kpeh, RTOT * ROPE_D / 4);

    // attention (fp16 MMA, fp32 softmax/accum) -> fp16 output
    flash_k<<<dim3(SS / FBM, HH, BB), 256, FLASH_SMEM>>>(qh, kvh, kpeh, oh);

    // output projection
    hgemm_k<<<dim3(DD / 128, RTOT / 128), 128, HG_SMEM>>>(oh, woT, out, RTOT, DD, HH * VD);
}

// round 14
// speedup vs baseline: 2.2388x; 1.1049x over previous
#include <cuda_runtime.h>
#include <cuda_fp16.h>
#include <math.h>
#include <stdint.h>

// Problem constants
#define BB 2
#define SS 2048
#define DD 2048
#define HH 16
#define NOPE 128
#define ROPE_D 64
#define VD 128
#define KV_RANK 512
#define Q_RANK 1536
#define QH (NOPE + ROPE_D)   // 192
#define KVH (NOPE + VD)      // 256
#define RTOT (BB * SS)       // 4096 rows

// ---------------- scratch (device globals, no allocation) ----------------
__device__ float g_cq [RTOT * Q_RANK];
__device__ float g_ckv[RTOT * (KV_RANK + ROPE_D)];
__device__ float g_cos[SS * (ROPE_D / 2)];
__device__ float g_sin[SS * (ROPE_D / 2)];
// fp16 operands (weights TRANSPOSED: [N][K] K-major)
__device__ __half g_xh  [RTOT * DD];
__device__ __half g_wdqT [Q_RANK * DD];
__device__ __half g_wuqT [HH * QH * Q_RANK];
__device__ __half g_wdkvT[(KV_RANK + ROPE_D) * DD];
__device__ __half g_wukvT[HH * KVH * KV_RANK];
__device__ __half g_woT  [DD * HH * VD];
__device__ __half g_cqh [RTOT * Q_RANK];
__device__ __half g_kvah[RTOT * KV_RANK];
__device__ __half g_oh  [RTOT * (HH * VD)];
__device__ __half g_qh  [RTOT * (HH * QH)];
__device__ __half g_kvh [RTOT * (HH * KVH)];
__device__ __half g_kpeh[RTOT * ROPE_D];

// ---------------- helpers -------------------------------------------------
__device__ __forceinline__ unsigned h2u(float a, float b) {
    __half2 h = __floats2half2_rn(a, b);
    return *(unsigned*)&h;
}

__device__ __forceinline__ void mma_f16(float c[4], const unsigned a[4], const unsigned b[2]) {
    asm volatile(
        "mma.sync.aligned.m16n8k16.row.col.f32.f16.f16.f32 "
        "{%0,%1,%2,%3}, {%4,%5,%6,%7}, {%8,%9}, {%0,%1,%2,%3};\n"
        : "+f"(c[0]), "+f"(c[1]), "+f"(c[2]), "+f"(c[3])
        : "r"(a[0]), "r"(a[1]), "r"(a[2]), "r"(a[3]), "r"(b[0]), "r"(b[1]));
}

__device__ __forceinline__ void ldmx4(unsigned& d0, unsigned& d1, unsigned& d2,
                                      unsigned& d3, uint32_t a) {
    asm volatile("ldmatrix.sync.aligned.m8n8.x4.shared.b16 {%0,%1,%2,%3}, [%4];"
                 : "=r"(d0), "=r"(d1), "=r"(d2), "=r"(d3) : "r"(a));
}
__device__ __forceinline__ void ldmx4t(unsigned& d0, unsigned& d1, unsigned& d2,
                                       unsigned& d3, uint32_t a) {
    asm volatile("ldmatrix.sync.aligned.m8n8.x4.trans.shared.b16 {%0,%1,%2,%3}, [%4];"
                 : "=r"(d0), "=r"(d1), "=r"(d2), "=r"(d3) : "r"(a));
}

__device__ __forceinline__ void cpa16(uint32_t dst_smem, const void* src) {
    asm volatile("cp.async.cg.shared.global [%0], [%1], 16;\n" :: "r"(dst_smem), "l"(src));
}
#define CP_COMMIT() asm volatile("cp.async.commit_group;\n")
#define CP_WAIT(n)  asm volatile("cp.async.wait_group %0;\n" :: "n"(n))

__device__ __forceinline__ uint32_t smem_u32(const void* p) {
    uint32_t a;
    asm("{ .reg .u64 t; cvta.to.shared.u64 t, %1; cvt.u32.u64 %0, t; }" : "=r"(a) : "l"(p));
    return a;
}

// ---------------- fp32 -> fp16 linear convert -----------------------------
__global__ void cvth_k(const float4* __restrict__ in, __half* __restrict__ out, int n4)
{
    int i = blockIdx.x * blockDim.x + threadIdx.x;
    int stride = gridDim.x * blockDim.x;
    for (; i < n4; i += stride) {
        float4 v = in[i];
        uint2 w;
        w.x = h2u(v.x, v.y);
        w.y = h2u(v.z, v.w);
        *(uint2*)(out + (size_t)i * 4) = w;
    }
}

// ---------------- transpose + fp16: in[R][C] fp32 -> out[C][R] half -------
__global__ __launch_bounds__(256) void trth_k(const float* __restrict__ in,
                                              __half* __restrict__ out, int R, int C)
{
    __shared__ float tl[32][33];
    int c0 = blockIdx.x * 32, r0 = blockIdx.y * 32;
    int tx = threadIdx.x & 31, ty = threadIdx.x >> 5;   // 32 x 8
#pragma unroll
    for (int k = 0; k < 4; k++)
        tl[ty + 8 * k][tx] = in[(size_t)(r0 + ty + 8 * k) * C + c0 + tx];
    __syncthreads();
#pragma unroll
    for (int k = 0; k < 4; k++)
        out[(size_t)(c0 + ty + 8 * k) * R + r0 + tx] = __float2half(tl[tx][ty + 8 * k]);
}

// ---------------- fp16 tensor-core GEMM core ------------------------------
// C = A(MxK) @ Bt(NxK)^T, ldmatrix frags, 128x128 CTA tile, BK=32 halves,
// 128 threads (4 warps, 64x64 warp tiles), double-buffered cp.async.
#define TBK 32
#define ASTR 40
#define HG_BUF (128 * ASTR)
#define HG_SMEM (4 * HG_BUF * 2)

#define HG_LOAD(tt, bufi)                                                      \
    do {                                                                       \
        const int kb = (tt) * TBK;                                             \
        const uint32_t ao = (bufi) * (HG_BUF * 2);                             \
        const uint32_t bo = 2 * (HG_BUF * 2) + (bufi) * (HG_BUF * 2);          \
        _Pragma("unroll")                                                      \
        for (int s = 0; s < 4; s++) {                                          \
            int ch = tid + 128 * s; int row = ch >> 2, cc = ch & 3;            \
            cpa16(sb + ao + (row * ASTR + cc * 8) * 2,                         \
                  A + (size_t)(m0 + row) * K + kb + cc * 8);                   \
            int rc = n0 + row; if (rc > N - 1) rc = N - 1;                     \
            cpa16(sb + bo + (row * ASTR + cc * 8) * 2,                         \
                  Bt + (size_t)rc * K + kb + cc * 8);                          \
        }                                                                      \
        CP_COMMIT();                                                           \
    } while (0)

#define HG_BODY                                                                \
    extern __shared__ __half smh[];                                            \
    const uint32_t sb = smem_u32(smh);                                         \
    const int tid  = threadIdx.x;                                              \
    const int lane = tid & 31;                                                 \
    const int warp = tid >> 5;                                                 \
    const int wm = warp & 1;                                                   \
    const int wn = warp >> 1;                                                  \
    const int g  = lane >> 2;                                                  \
    const int tg = lane & 3;                                                   \
    const int n0 = blockIdx.x * 128;                                           \
    const int m0 = blockIdx.y * 128;                                           \
    const int lm = lane >> 3, lr8 = lane & 7;                                  \
    const int aRowOff = (lm & 1) * 8 + lr8;                                    \
    const int aKOff   = (lm >> 1) * 8;                                         \
    const int bRowOff = (lm >> 1) * 8 + lr8;                                   \
    const int bKOff   = (lm & 1) * 8;                                          \
    float acc[4][8][4];                                                        \
    _Pragma("unroll")                                                          \
    for (int i = 0; i < 4; i++)                                                \
        _Pragma("unroll")                                                      \
        for (int j = 0; j < 8; j++)                                            \
            _Pragma("unroll")                                                  \
            for (int e = 0; e < 4; e++) acc[i][j][e] = 0.f;                    \
    const int nt = K / TBK;                                                    \
    HG_LOAD(0, 0);                                                             \
    for (int t = 0; t < nt; t++) {                                             \
        const int buf = t & 1;                                                 \
        if (t + 1 < nt) { HG_LOAD(t + 1, buf ^ 1); CP_WAIT(1); }               \
        else { CP_WAIT(0); }                                                   \
        __syncthreads();                                                       \
        const uint32_t abase = sb + buf * (HG_BUF * 2);                        \
        const uint32_t bbase = sb + 2 * (HG_BUF * 2) + buf * (HG_BUF * 2);     \
        _Pragma("unroll")                                                      \
        for (int kc = 0; kc < 2; kc++) {                                       \
            unsigned af[4][4], bf[8][2];                                       \
            _Pragma("unroll")                                                  \
            for (int i = 0; i < 4; i++) {                                      \
                uint32_t a = abase + (uint32_t)(((wm * 64 + i * 16 + aRowOff) * ASTR \
                                                + kc * 16 + aKOff) * 2);       \
                ldmx4(af[i][0], af[i][1], af[i][2], af[i][3], a);              \
            }                                                                  \
            _Pragma("unroll")                                                  \
            for (int jj = 0; jj < 4; jj++) {                                   \
                uint32_t a = bbase + (uint32_t)(((wn * 64 + jj * 16 + bRowOff) * ASTR \
                                                + kc * 16 + bKOff) * 2);       \
                ldmx4(bf[2 * jj][0], bf[2 * jj][1], bf[2 * jj + 1][0], bf[2 * jj + 1][1], a); \
            }                                                                  \
            _Pragma("unroll")                                                  \
            for (int i = 0; i < 4; i++)                                        \
                _Pragma("unroll")                                              \
                for (int j = 0; j < 8; j++)                                    \
                    mma_f16(acc[i][j], af[i], bf[j]);                          \
        }                                                                      \
        __syncthreads();                                                       \
    }

__global__ __launch_bounds__(128, 2) void hgemm_k(
    const __half* __restrict__ A, const __half* __restrict__ Bt,
    float* __restrict__ C, int M, int N, int K)
{
    HG_BODY
#pragma unroll
    for (int i = 0; i < 4; i++) {
        const int r0 = m0 + wm * 64 + i * 16 + g;
#pragma unroll
        for (int j = 0; j < 8; j++) {
            const int c = n0 + wn * 64 + j * 8 + 2 * tg;
            if (c < N) {
                *(float2*)(C + (size_t)r0 * N + c) = make_float2(acc[i][j][0], acc[i][j][1]);
                *(float2*)(C + (size_t)(r0 + 8) * N + c) = make_float2(acc[i][j][2], acc[i][j][3]);
            }
        }
    }
}

__global__ __launch_bounds__(128, 2) void hgemmh_k(
    const __half* __restrict__ A, const __half* __restrict__ Bt,
    __half* __restrict__ C, int M, int N, int K)
{
    HG_BODY
#pragma unroll
    for (int i = 0; i < 4; i++) {
        const int r0 = m0 + wm * 64 + i * 16 + g;
#pragma unroll
        for (int j = 0; j < 8; j++) {
            const int c = n0 + wn * 64 + j * 8 + 2 * tg;
            if (c < N) {
                *(unsigned*)(C + (size_t)r0 * N + c) = h2u(acc[i][j][0], acc[i][j][1]);
                *(unsigned*)(C + (size_t)(r0 + 8) * N + c) = h2u(acc[i][j][2], acc[i][j][3]);
            }
        }
    }
}

// ---------------- RMSNorm (fp32 in -> fp16 out) ---------------------------
__global__ void rmsnorm_k(const float* in, __half* out, const float* __restrict__ w,
                          int cols, int in_stride, int out_stride)
{
    const int row = blockIdx.x;
    const float* xi = in + (size_t)row * in_stride;
    float s = 0.f;
    for (int c = threadIdx.x; c < cols; c += blockDim.x) {
        float v = xi[c];
        s += v * v;
    }
    __shared__ float red[8];
#pragma unroll
    for (int o = 16; o > 0; o >>= 1) s += __shfl_down_sync(0xffffffffu, s, o);
    int warp = threadIdx.x >> 5, lane = threadIdx.x & 31;
    if (lane == 0) red[warp] = s;
    __syncthreads();
    if (warp == 0) {
        s = (lane < (blockDim.x >> 5)) ? red[lane] : 0.f;
#pragma unroll
        for (int o = 4; o > 0; o >>= 1) s += __shfl_down_sync(0xffffffffu, s, o);
        if (lane == 0) red[0] = s;
    }
    __syncthreads();
    float r = rsqrtf(red[0] / (float)cols + 1e-6f);
    __half* yo = out + (size_t)row * out_stride;
    for (int c = threadIdx.x; c < cols; c += blockDim.x)
        yo[c] = __float2half(xi[c] * r * w[c]);
}

// ---------------- RoPE ---------------------------------------------------
__global__ void rope_table_k(float* ct, float* st)
{
    int s = blockIdx.x, i = threadIdx.x;
    double inv = exp(-((double)(2 * i) / 64.0) * log(10000.0));
    double ang = (double)s * inv;
    ct[s * 32 + i] = (float)cos(ang);
    st[s * 32 + i] = (float)sin(ang);
}

// RoPE in-place on half q (pe slice of each head)
__global__ void rope_qh_k(__half* Q, const float* __restrict__ ct, const float* __restrict__ st)
{
    int bs = blockIdx.x;
    int s = bs & (SS - 1);
    int i = threadIdx.x;
    int h = threadIdx.y;
    size_t base = ((size_t)bs * HH + h) * QH + NOPE;
    float c = ct[s * 32 + i], sn = st[s * 32 + i];
    float x1 = __half2float(Q[base + i]), x2 = __half2float(Q[base + 32 + i]);
    Q[base + i]      = __float2half(x1 * c - x2 * sn);
    Q[base + 32 + i] = __float2half(x2 * c + x1 * sn);
}

// RoPE: fp32 ckv pe slice -> half kpe
__global__ void rope_kh_k(const float* __restrict__ CKV, __half* KPE,
                          const float* __restrict__ ct, const float* __restrict__ st)
{
    int bs = blockIdx.x;
    int s = bs & (SS - 1);
    int i = threadIdx.x;
    const float* src = CKV + (size_t)bs * (KV_RANK + ROPE_D) + KV_RANK;
    float c = ct[s * 32 + i], sn = st[s * 32 + i];
    float x1 = src[i], x2 = src[32 + i];
    KPE[(size_t)bs * ROPE_D + i]      = __float2half(x1 * c - x2 * sn);
    KPE[(size_t)bs * ROPE_D + 32 + i] = __float2half(x2 * c + x1 * sn);
}

// ---------------- fp16 tensor-core causal flash attention -----------------
// 256 threads = 8 warps; warp w owns query rows q0 + 16w + {g, g+8}.
// K/V staged by double-buffered cp.async 64-key tiles; K-frags via
// ldmatrix.x4, V-frags via ldmatrix.x4.trans. Scale post-MMA in fp32.
#define FBM 128
#define FBN 64
#define KSTR 200      // halves; 400B rows (16 mod 128): conflict-free
#define VSTR 136      // halves; 272B rows (16 mod 128): conflict-free
#define KELE (FBN * KSTR)
#define VELE (FBN * VSTR)
#define FLASH_SMEM (2 * (KELE + VELE) * 2)

__global__ __launch_bounds__(256) void flash_k(
    const __half* __restrict__ QH_g, const __half* __restrict__ KVH_g,
    const __half* __restrict__ KPEH_g, __half* __restrict__ OH)
{
    extern __shared__ __half smf[];
    const uint32_t sbase = smem_u32(smf);

    const int q0 = blockIdx.x * FBM;
    const int h = blockIdx.y;
    const int b = blockIdx.z;
    const int t = threadIdx.x;
    const int warp = t >> 5;
    const int lane = t & 31;
    const int g = lane >> 2;
    const int tg = lane & 3;
    const int row0 = warp * 16 + g;
    const float scale = rsqrtf((float)QH);

    // ldmatrix lane addressing
    const int lm = lane >> 3, lr8 = lane & 7;
    const int kRowOff = (lm >> 1) * 8 + lr8;   // K frags (non-trans)
    const int kKOff   = (lm & 1) * 8;
    const int vK      = (lm & 1) * 8 + lr8;    // V frags (trans)
    const int vC      = (lm >> 1) * 8;

    // persistent Q A-frags
    unsigned aq[12][4];
    {
        const unsigned* qp0 = (const unsigned*)(QH_g + ((size_t)(b * SS + q0 + row0) * HH + h) * QH);
        const unsigned* qp1 = qp0 + (size_t)8 * HH * QH / 2;
#pragma unroll
        for (int kc = 0; kc < 12; kc++) {
            aq[kc][0] = qp0[kc * 8 + tg];
            aq[kc][1] = qp1[kc * 8 + tg];
            aq[kc][2] = qp0[kc * 8 + tg + 4];
            aq[kc][3] = qp1[kc * 8 + tg + 4];
        }
    }

    float oacc[16][4];
#pragma unroll
    for (int i = 0; i < 16; i++)
#pragma unroll
        for (int e = 0; e < 4; e++) oacc[i][e] = 0.f;
    float m0 = -3.0e38f, m1 = -3.0e38f, l0 = 0.f, l1 = 0.f;

    const int flr = t >> 2;
    const int q4 = t & 3;
    const int ntiles = (q0 + FBM) / FBN;

#define FL_LOAD(tt, bufi)                                                          \
    do {                                                                           \
        const int kk0 = (tt) * FBN;                                                \
        const __half* kvrow = KVH_g + ((size_t)(b * SS + kk0 + flr) * HH + h) * KVH;\
        const __half* kprow = KPEH_g + (size_t)(b * SS + kk0 + flr) * ROPE_D;      \
        const uint32_t kdst = sbase + (bufi) * (KELE * 2) + flr * (KSTR * 2);      \
        const uint32_t vdst = sbase + 2 * (KELE * 2) + (bufi) * (VELE * 2)         \
                              + flr * (VSTR * 2);                                  \
        _Pragma("unroll")                                                          \
        for (int i = 0; i < 6; i++) {                                              \
            int c = q4 * 6 + i;                                                    \
            const __half* src = (c < 16) ? kvrow + c * 8 : kprow + (c - 16) * 8;   \
            cpa16(kdst + c * 16, src);                                             \
        }                                                                          \
        _Pragma("unroll")                                                          \
        for (int i = 0; i < 4; i++) {                                              \
            int c = q4 * 4 + i;                                                    \
            cpa16(vdst + c * 16, kvrow + 128 + c * 8);                             \
        }                                                                          \
        CP_COMMIT();                                                               \
    } while (0)

    FL_LOAD(0, 0);

    for (int tile = 0; tile < ntiles; tile++) {
        const int k0 = tile * FBN;
        const int buf = tile & 1;
        if (tile + 1 < ntiles) {
            FL_LOAD(tile + 1, buf ^ 1);
            CP_WAIT(1);
        } else {
            CP_WAIT(0);
        }
        __syncthreads();

        if (k0 <= q0 + warp * 16 + 15) {
            const uint32_t kb2 = sbase + buf * (KELE * 2);
            const uint32_t vb = sbase + 2 * (KELE * 2) + buf * (VELE * 2);

            // QK^T with ldmatrix.x4 K-frags
            float c[8][4];
#pragma unroll
            for (int nb = 0; nb < 8; nb++)
#pragma unroll
                for (int e = 0; e < 4; e++) c[nb][e] = 0.f;
#pragma unroll
            for (int kc = 0; kc < 12; kc++) {
#pragma unroll
                for (int n16 = 0; n16 < 4; n16++) {
                    uint32_t a = kb2 + (uint32_t)(((n16 * 16 + kRowOff) * KSTR
                                                  + kc * 16 + kKOff) * 2);
                    unsigned b0, b1, b2, b3;
                    ldmx4(b0, b1, b2, b3, a);
                    unsigned bf0[2] = {b0, b1};
                    unsigned bf1[2] = {b2, b3};
                    mma_f16(c[2 * n16], aq[kc], bf0);
                    mma_f16(c[2 * n16 + 1], aq[kc], bf1);
                }
            }
            // scale in fp32
#pragma unroll
            for (int nb = 0; nb < 8; nb++)
#pragma unroll
                for (int e = 0; e < 4; e++) c[nb][e] *= scale;

            // causal mask
            if (k0 + FBN - 1 > q0 + warp * 16) {
                const int r0g = q0 + warp * 16 + g;
#pragma unroll
                for (int nb = 0; nb < 8; nb++) {
                    int col = k0 + nb * 8 + 2 * tg;
                    if (col     > r0g)     c[nb][0] = -3.0e38f;
                    if (col + 1 > r0g)     c[nb][1] = -3.0e38f;
                    if (col     > r0g + 8) c[nb][2] = -3.0e38f;
                    if (col + 1 > r0g + 8) c[nb][3] = -3.0e38f;
                }
            }

            // online softmax
            float tm0 = -3.0e38f, tm1 = -3.0e38f;
#pragma unroll
            for (int nb = 0; nb < 8; nb++) {
                tm0 = fmaxf(tm0, fmaxf(c[nb][0], c[nb][1]));
                tm1 = fmaxf(tm1, fmaxf(c[nb][2], c[nb][3]));
            }
            tm0 = fmaxf(tm0, __shfl_xor_sync(0xffffffffu, tm0, 1));
            tm0 = fmaxf(tm0, __shfl_xor_sync(0xffffffffu, tm0, 2));
            tm1 = fmaxf(tm1, __shfl_xor_sync(0xffffffffu, tm1, 1));
            tm1 = fmaxf(tm1, __shfl_xor_sync(0xffffffffu, tm1, 2));

            float nm0 = fmaxf(m0, tm0), nm1 = fmaxf(m1, tm1);
            float co0 = __expf(m0 - nm0), co1 = __expf(m1 - nm1);
            l0 *= co0; l1 *= co1;
#pragma unroll
            for (int nb = 0; nb < 16; nb++) {
                oacc[nb][0] *= co0; oacc[nb][1] *= co0;
                oacc[nb][2] *= co1; oacc[nb][3] *= co1;
            }
            m0 = nm0; m1 = nm1;

            float ls0 = 0.f, ls1 = 0.f;
#pragma unroll
            for (int nb = 0; nb < 8; nb++) {
                c[nb][0] = __expf(c[nb][0] - nm0);
                c[nb][1] = __expf(c[nb][1] - nm0);
                c[nb][2] = __expf(c[nb][2] - nm1);
                c[nb][3] = __expf(c[nb][3] - nm1);
                ls0 += c[nb][0] + c[nb][1];
                ls1 += c[nb][2] + c[nb][3];
            }
            ls0 += __shfl_xor_sync(0xffffffffu, ls0, 1);
            ls0 += __shfl_xor_sync(0xffffffffu, ls0, 2);
            ls1 += __shfl_xor_sync(0xffffffffu, ls1, 1);
            ls1 += __shfl_xor_sync(0xffffffffu, ls1, 2);
            l0 += ls0; l1 += ls1;

            // P @ V with ldmatrix.x4.trans V-frags
#pragma unroll
            for (int kr = 0; kr < 4; kr++) {
                unsigned ap[4];
                ap[0] = h2u(c[2 * kr][0],     c[2 * kr][1]);
                ap[1] = h2u(c[2 * kr][2],     c[2 * kr][3]);
                ap[2] = h2u(c[2 * kr + 1][0], c[2 * kr + 1][1]);
                ap[3] = h2u(c[2 * kr + 1][2], c[2 * kr + 1][3]);
                const uint32_t krowb = vb + (uint32_t)((kr * 16 + vK) * (VSTR * 2));
#pragma unroll
                for (int np = 0; np < 8; np++) {
                    uint32_t a = krowb + (uint32_t)((np * 16 + vC) * 2);
                    unsigned b0, b1, b2, b3;
                    ldmx4t(b0, b1, b2, b3, a);
                    unsigned bv0[2] = {b0, b1};
                    unsigned bv1[2] = {b2, b3};
                    mma_f16(oacc[2 * np], ap, bv0);
                    mma_f16(oacc[2 * np + 1], ap, bv1);
                }
            }
        }
        __syncthreads();
    }

    // epilogue: fp16 output
    float inv0 = 1.f / l0, inv1 = 1.f / l1;
    __half* o0 = OH + ((size_t)(b * SS + q0 + row0) * HH + h) * VD;
    __half* o1 = o0 + (size_t)8 * HH * VD;
#pragma unroll
    for (int nb = 0; nb < 16; nb++) {
        *(unsigned*)(o0 + nb * 8 + 2 * tg) = h2u(oacc[nb][0] * inv0, oacc[nb][1] * inv0);
        *(unsigned*)(o1 + nb * 8 + 2 * tg) = h2u(oacc[nb][2] * inv1, oacc[nb][3] * inv1);
    }
}

// ---------------- host launcher ------------------------------------------
extern "C" void kernel_launch(void* const* d_in, const int* in_sizes, int n_in,
                              void* d_out, int out_size)
{
    const float* x         = (const float*)d_in[0];
    const float* w_dq      = (const float*)d_in[1];
    const float* q_a_norm  = (const float*)d_in[2];
    const float* w_uq      = (const float*)d_in[3];
    const float* w_dkv     = (const float*)d_in[4];
    const float* kv_a_norm = (const float*)d_in[5];
    const float* w_ukv     = (const float*)d_in[6];
    const float* w_o       = (const float*)d_in[7];
    float* out = (float*)d_out;

    float *cq, *ckv, *ct, *st;
    __half *xh, *wdqT, *wuqT, *wdkvT, *wukvT, *woT, *cqh, *kvah, *oh, *qh, *kvh, *kpeh;
    cudaGetSymbolAddress((void**)&cq,  g_cq);
    cudaGetSymbolAddress((void**)&ckv, g_ckv);
    cudaGetSymbolAddress((void**)&ct,  g_cos);
    cudaGetSymbolAddress((void**)&st,  g_sin);
    cudaGetSymbolAddress((void**)&xh,    g_xh);
    cudaGetSymbolAddress((void**)&wdqT,  g_wdqT);
    cudaGetSymbolAddress((void**)&wuqT,  g_wuqT);
    cudaGetSymbolAddress((void**)&wdkvT, g_wdkvT);
    cudaGetSymbolAddress((void**)&wukvT, g_wukvT);
    cudaGetSymbolAddress((void**)&woT,   g_woT);
    cudaGetSymbolAddress((void**)&cqh,   g_cqh);
    cudaGetSymbolAddress((void**)&kvah,  g_kvah);
    cudaGetSymbolAddress((void**)&oh,    g_oh);
    cudaGetSymbolAddress((void**)&qh,    g_qh);
    cudaGetSymbolAddress((void**)&kvh,   g_kvh);
    cudaGetSymbolAddress((void**)&kpeh,  g_kpeh);

    cudaFuncSetAttribute(hgemm_k,  cudaFuncAttributeMaxDynamicSharedMemorySize, HG_SMEM);
    cudaFuncSetAttribute(hgemmh_k, cudaFuncAttributeMaxDynamicSharedMemorySize, HG_SMEM);
    cudaFuncSetAttribute(flash_k,  cudaFuncAttributeMaxDynamicSharedMemorySize, FLASH_SMEM);

    rope_table_k<<<SS, 32>>>(ct, st);

    // convert A operand; transpose+convert weights to [N][K] half
    cvth_k<<<592, 256>>>((const float4*)x, xh, RTOT * DD / 4);
    trth_k<<<dim3(Q_RANK / 32, DD / 32), 256>>>(w_dq, wdqT, DD, Q_RANK);
    trth_k<<<dim3((HH * QH) / 32, Q_RANK / 32), 256>>>(w_uq, wuqT, Q_RANK, HH * QH);
    trth_k<<<dim3((KV_RANK + ROPE_D) / 32, DD / 32), 256>>>(w_dkv, wdkvT, DD, KV_RANK + ROPE_D);
    trth_k<<<dim3((HH * KVH) / 32, KV_RANK / 32), 256>>>(w_ukv, wukvT, KV_RANK, HH * KVH);
    trth_k<<<dim3(DD / 32, (HH * VD) / 32), 256>>>(w_o, woT, HH * VD, DD);

    // q path: cq fp32 -> rmsnorm -> half -> q GEMM writes half directly
    hgemm_k<<<dim3(Q_RANK / 128, RTOT / 128), 128, HG_SMEM>>>(xh, wdqT, cq, RTOT, Q_RANK, DD);
    rmsnorm_k<<<RTOT, 256>>>(cq, cqh, q_a_norm, Q_RANK, Q_RANK, Q_RANK);
    hgemmh_k<<<dim3((HH * QH) / 128, RTOT / 128), 128, HG_SMEM>>>(cqh, wuqT, qh, RTOT, HH * QH, Q_RANK);

    // kv path: ckv fp32 -> rmsnorm -> half -> kv GEMM writes half directly
    hgemm_k<<<dim3((KV_RANK + ROPE_D + 127) / 128, RTOT / 128), 128, HG_SMEM>>>(
        xh, wdkvT, ckv, RTOT, KV_RANK + ROPE_D, DD);
    rmsnorm_k<<<RTOT, 256>>>(ckv, kvah, kv_a_norm, KV_RANK, KV_RANK + ROPE_D, KV_RANK);
    hgemmh_k<<<dim3((HH * KVH) / 128, RTOT / 128), 128, HG_SMEM>>>(kvah, wukvT, kvh, RTOT, HH * KVH, KV_RANK);

    // RoPE: q in-place on half; k_pe fp32 ckv -> half
    rope_qh_k<<<RTOT, dim3(32, HH)>>>(qh, ct, st);
    rope_kh_k<<<RTOT, 32>>>(ckv, kpeh, ct, st);

    // attention (fp16 MMA, fp32 softmax/accum) -> fp16 output
    flash_k<<<dim3(SS / FBM, HH, BB), 256, FLASH_SMEM>>>(qh, kvh, kpeh, oh);

    // output projection
    hgemm_k<<<dim3(DD / 128, RTOT / 128), 128, HG_SMEM>>>(oh, woT, out, RTOT, DD, HH * VD);
}

// round 15
// speedup vs baseline: 2.2942x; 1.0247x over previous
#include <cuda_runtime.h>
#include <cuda_fp16.h>
#include <math.h>
#include <stdint.h>

// Problem constants
#define BB 2
#define SS 2048
#define DD 2048
#define HH 16
#define NOPE 128
#define ROPE_D 64
#define VD 128
#define KV_RANK 512
#define Q_RANK 1536
#define QH (NOPE + ROPE_D)   // 192
#define KVH (NOPE + VD)      // 256
#define RTOT (BB * SS)       // 4096 rows
#define N1 (Q_RANK + KV_RANK + ROPE_D)   // 2112: merged x-projection width

// ---------------- scratch (device globals, no allocation) ----------------
__device__ float g_c1 [RTOT * N1];          // merged x@[w_dq|w_dkv] output (fp32)
__device__ float g_cos[SS * (ROPE_D / 2)];
__device__ float g_sin[SS * (ROPE_D / 2)];
// fp16 operands (weights TRANSPOSED: [N][K] K-major)
__device__ __half g_xh  [RTOT * DD];
__device__ __half g_w1T [N1 * DD];          // rows 0..1535 = wdqT, 1536..2111 = wdkvT
__device__ __half g_wuqT [HH * QH * Q_RANK];
__device__ __half g_wukvT[HH * KVH * KV_RANK];
__device__ __half g_woT  [DD * HH * VD];
__device__ __half g_cqh [RTOT * Q_RANK];
__device__ __half g_kvah[RTOT * KV_RANK];
__device__ __half g_oh  [RTOT * (HH * VD)];
__device__ __half g_qh  [RTOT * (HH * QH)];
__device__ __half g_kvh [RTOT * (HH * KVH)];
__device__ __half g_kpeh[RTOT * ROPE_D];

// ---------------- helpers -------------------------------------------------
__device__ __forceinline__ unsigned h2u(float a, float b) {
    __half2 h = __floats2half2_rn(a, b);
    return *(unsigned*)&h;
}

__device__ __forceinline__ void mma_f16(float c[4], const unsigned a[4], const unsigned b[2]) {
    asm volatile(
        "mma.sync.aligned.m16n8k16.row.col.f32.f16.f16.f32 "
        "{%0,%1,%2,%3}, {%4,%5,%6,%7}, {%8,%9}, {%0,%1,%2,%3};\n"
        : "+f"(c[0]), "+f"(c[1]), "+f"(c[2]), "+f"(c[3])
        : "r"(a[0]), "r"(a[1]), "r"(a[2]), "r"(a[3]), "r"(b[0]), "r"(b[1]));
}

__device__ __forceinline__ void ldmx4(unsigned& d0, unsigned& d1, unsigned& d2,
                                      unsigned& d3, uint32_t a) {
    asm volatile("ldmatrix.sync.aligned.m8n8.x4.shared.b16 {%0,%1,%2,%3}, [%4];"
                 : "=r"(d0), "=r"(d1), "=r"(d2), "=r"(d3) : "r"(a));
}
__device__ __forceinline__ void ldmx4t(unsigned& d0, unsigned& d1, unsigned& d2,
                                       unsigned& d3, uint32_t a) {
    asm volatile("ldmatrix.sync.aligned.m8n8.x4.trans.shared.b16 {%0,%1,%2,%3}, [%4];"
                 : "=r"(d0), "=r"(d1), "=r"(d2), "=r"(d3) : "r"(a));
}

__device__ __forceinline__ void cpa16(uint32_t dst_smem, const void* src) {
    asm volatile("cp.async.cg.shared.global [%0], [%1], 16;\n" :: "r"(dst_smem), "l"(src));
}
#define CP_COMMIT() asm volatile("cp.async.commit_group;\n")
#define CP_WAIT(n)  asm volatile("cp.async.wait_group %0;\n" :: "n"(n))

__device__ __forceinline__ uint32_t smem_u32(const void* p) {
    uint32_t a;
    asm("{ .reg .u64 t; cvta.to.shared.u64 t, %1; cvt.u32.u64 %0, t; }" : "=r"(a) : "l"(p));
    return a;
}

// ---------------- fp32 -> fp16 linear convert -----------------------------
__global__ void cvth_k(const float4* __restrict__ in, __half* __restrict__ out, int n4)
{
    int i = blockIdx.x * blockDim.x + threadIdx.x;
    int stride = gridDim.x * blockDim.x;
    for (; i < n4; i += stride) {
        float4 v = in[i];
        uint2 w;
        w.x = h2u(v.x, v.y);
        w.y = h2u(v.z, v.w);
        *(uint2*)(out + (size_t)i * 4) = w;
    }
}

// ---------------- transpose + fp16: in[R][C] fp32 -> out[C][R] half -------
__global__ __launch_bounds__(256) void trth_k(const float* __restrict__ in,
                                              __half* __restrict__ out, int R, int C)
{
    __shared__ float tl[32][33];
    int c0 = blockIdx.x * 32, r0 = blockIdx.y * 32;
    int tx = threadIdx.x & 31, ty = threadIdx.x >> 5;   // 32 x 8
#pragma unroll
    for (int k = 0; k < 4; k++)
        tl[ty + 8 * k][tx] = in[(size_t)(r0 + ty + 8 * k) * C + c0 + tx];
    __syncthreads();
#pragma unroll
    for (int k = 0; k < 4; k++)
        out[(size_t)(c0 + ty + 8 * k) * R + r0 + tx] = __float2half(tl[tx][ty + 8 * k]);
}

// ---------------- fp16 tensor-core GEMM core ------------------------------
// C = A(MxK) @ Bt(NxK)^T, ldmatrix frags, 128x128 CTA tile, BK=64 halves,
// 128 threads (4 warps, 64x64 warp tiles), double-buffered cp.async.
// M%128==0, K%64==0.
#define TBK 64
#define ASTR 72                        // halves; 144B rows, conflict-free
#define HG_BUF (128 * ASTR)
#define HG_SMEM (4 * HG_BUF * 2)       // 73728 bytes

#define HG_LOAD(tt, bufi)                                                      \
    do {                                                                       \
        const int kb = (tt) * TBK;                                             \
        const uint32_t ao = (bufi) * (HG_BUF * 2);                             \
        const uint32_t bo = 2 * (HG_BUF * 2) + (bufi) * (HG_BUF * 2);          \
        _Pragma("unroll")                                                      \
        for (int s = 0; s < 8; s++) {                                          \
            int ch = tid + 128 * s; int row = ch >> 3, cc = ch & 7;            \
            cpa16(sb + ao + (row * ASTR + cc * 8) * 2,                         \
                  A + (size_t)(m0 + row) * K + kb + cc * 8);                   \
            int rc = n0 + row; if (rc > N - 1) rc = N - 1;                     \
            cpa16(sb + bo + (row * ASTR + cc * 8) * 2,                         \
                  Bt + (size_t)rc * K + kb + cc * 8);                          \
        }                                                                      \
        CP_COMMIT();                                                           \
    } while (0)

#define HG_BODY                                                                \
    extern __shared__ __half smh[];                                            \
    const uint32_t sb = smem_u32(smh);                                         \
    const int tid  = threadIdx.x;                                              \
    const int lane = tid & 31;                                                 \
    const int warp = tid >> 5;                                                 \
    const int wm = warp & 1;                                                   \
    const int wn = warp >> 1;                                                  \
    const int g  = lane >> 2;                                                  \
    const int tg = lane & 3;                                                   \
    const int n0 = blockIdx.x * 128;                                           \
    const int m0 = blockIdx.y * 128;                                           \
    const int lm = lane >> 3, lr8 = lane & 7;                                  \
    const int aRowOff = (lm & 1) * 8 + lr8;                                    \
    const int aKOff   = (lm >> 1) * 8;                                         \
    const int bRowOff = (lm >> 1) * 8 + lr8;                                   \
    const int bKOff   = (lm & 1) * 8;                                          \
    float acc[4][8][4];                                                        \
    _Pragma("unroll")                                                          \
    for (int i = 0; i < 4; i++)                                                \
        _Pragma("unroll")                                                      \
        for (int j = 0; j < 8; j++)                                            \
            _Pragma("unroll")                                                  \
            for (int e = 0; e < 4; e++) acc[i][j][e] = 0.f;                    \
    const int nt = K / TBK;                                                    \
    HG_LOAD(0, 0);                                                             \
    for (int t = 0; t < nt; t++) {                                             \
        const int buf = t & 1;                                                 \
        if (t + 1 < nt) { HG_LOAD(t + 1, buf ^ 1); CP_WAIT(1); }               \
        else { CP_WAIT(0); }                                                   \
        __syncthreads();                                                       \
        const uint32_t abase = sb + buf * (HG_BUF * 2);                        \
        const uint32_t bbase = sb + 2 * (HG_BUF * 2) + buf * (HG_BUF * 2);     \
        _Pragma("unroll")                                                      \
        for (int kc = 0; kc < 4; kc++) {                                       \
            unsigned af[4][4], bf[8][2];                                       \
            _Pragma("unroll")                                                  \
            for (int i = 0; i < 4; i++) {                                      \
                uint32_t a = abase + (uint32_t)(((wm * 64 + i * 16 + aRowOff) * ASTR \
                                                + kc * 16 + aKOff) * 2);       \
                ldmx4(af[i][0], af[i][1], af[i][2], af[i][3], a);              \
            }                                                                  \
            _Pragma("unroll")                                                  \
            for (int jj = 0; jj < 4; jj++) {                                   \
                uint32_t a = bbase + (uint32_t)(((wn * 64 + jj * 16 + bRowOff) * ASTR \
                                                + kc * 16 + bKOff) * 2);       \
                ldmx4(bf[2 * jj][0], bf[2 * jj][1], bf[2 * jj + 1][0], bf[2 * jj + 1][1], a); \
            }                                                                  \
            _Pragma("unroll")                                                  \
            for (int i = 0; i < 4; i++)                                        \
                _Pragma("unroll")                                              \
                for (int j = 0; j < 8; j++)                                    \
                    mma_f16(acc[i][j], af[i], bf[j]);                          \
        }                                                                      \
        __syncthreads();                                                       \
    }

__global__ __launch_bounds__(128, 2) void hgemm_k(
    const __half* __restrict__ A, const __half* __restrict__ Bt,
    float* __restrict__ C, int M, int N, int K)
{
    HG_BODY
#pragma unroll
    for (int i = 0; i < 4; i++) {
        const int r0 = m0 + wm * 64 + i * 16 + g;
#pragma unroll
        for (int j = 0; j < 8; j++) {
            const int c = n0 + wn * 64 + j * 8 + 2 * tg;
            if (c < N) {
                *(float2*)(C + (size_t)r0 * N + c) = make_float2(acc[i][j][0], acc[i][j][1]);
                *(float2*)(C + (size_t)(r0 + 8) * N + c) = make_float2(acc[i][j][2], acc[i][j][3]);
            }
        }
    }
}

__global__ __launch_bounds__(128, 2) void hgemmh_k(
    const __half* __restrict__ A, const __half* __restrict__ Bt,
    __half* __restrict__ C, int M, int N, int K)
{
    HG_BODY
#pragma unroll
    for (int i = 0; i < 4; i++) {
        const int r0 = m0 + wm * 64 + i * 16 + g;
#pragma unroll
        for (int j = 0; j < 8; j++) {
            const int c = n0 + wn * 64 + j * 8 + 2 * tg;
            if (c < N) {
                *(unsigned*)(C + (size_t)r0 * N + c) = h2u(acc[i][j][0], acc[i][j][1]);
                *(unsigned*)(C + (size_t)(r0 + 8) * N + c) = h2u(acc[i][j][2], acc[i][j][3]);
            }
        }
    }
}

// ---------------- RMSNorm (fp32 in -> fp16 out) ---------------------------
__global__ void rmsnorm_k(const float* in, __half* out, const float* __restrict__ w,
                          int cols, int in_stride, int out_stride)
{
    const int row = blockIdx.x;
    const float* xi = in + (size_t)row * in_stride;
    float s = 0.f;
    for (int c = threadIdx.x; c < cols; c += blockDim.x) {
        float v = xi[c];
        s += v * v;
    }
    __shared__ float red[8];
#pragma unroll
    for (int o = 16; o > 0; o >>= 1) s += __shfl_down_sync(0xffffffffu, s, o);
    int warp = threadIdx.x >> 5, lane = threadIdx.x & 31;
    if (lane == 0) red[warp] = s;
    __syncthreads();
    if (warp == 0) {
        s = (lane < (blockDim.x >> 5)) ? red[lane] : 0.f;
#pragma unroll
        for (int o = 4; o > 0; o >>= 1) s += __shfl_down_sync(0xffffffffu, s, o);
        if (lane == 0) red[0] = s;
    }
    __syncthreads();
    float r = rsqrtf(red[0] / (float)cols + 1e-6f);
    __half* yo = out + (size_t)row * out_stride;
    for (int c = threadIdx.x; c < cols; c += blockDim.x)
        yo[c] = __float2half(xi[c] * r * w[c]);
}

// ---------------- RoPE ---------------------------------------------------
__global__ void rope_table_k(float* ct, float* st)
{
    int s = blockIdx.x, i = threadIdx.x;
    double inv = exp(-((double)(2 * i) / 64.0) * log(10000.0));
    double ang = (double)s * inv;
    ct[s * 32 + i] = (float)cos(ang);
    st[s * 32 + i] = (float)sin(ang);
}

// RoPE in-place on half q (pe slice of each head)
__global__ void rope_qh_k(__half* Q, const float* __restrict__ ct, const float* __restrict__ st)
{
    int bs = blockIdx.x;
    int s = bs & (SS - 1);
    int i = threadIdx.x;
    int h = threadIdx.y;
    size_t base = ((size_t)bs * HH + h) * QH + NOPE;
    float c = ct[s * 32 + i], sn = st[s * 32 + i];
    float x1 = __half2float(Q[base + i]), x2 = __half2float(Q[base + 32 + i]);
    Q[base + i]      = __float2half(x1 * c - x2 * sn);
    Q[base + 32 + i] = __float2half(x2 * c + x1 * sn);
}

// RoPE: fp32 pe slice (strided source) -> half kpe
__global__ void rope_kh_k(const float* __restrict__ PE, int pe_stride, __half* KPE,
                          const float* __restrict__ ct, const float* __restrict__ st)
{
    int bs = blockIdx.x;
    int s = bs & (SS - 1);
    int i = threadIdx.x;
    const float* src = PE + (size_t)bs * pe_stride;
    float c = ct[s * 32 + i], sn = st[s * 32 + i];
    float x1 = src[i], x2 = src[32 + i];
    KPE[(size_t)bs * ROPE_D + i]      = __float2half(x1 * c - x2 * sn);
    KPE[(size_t)bs * ROPE_D + 32 + i] = __float2half(x2 * c + x1 * sn);
}

// ---------------- fp16 tensor-core causal flash attention -----------------
#define FBM 128
#define FBN 64
#define KSTR 200      // halves; 400B rows (16 mod 128): conflict-free
#define VSTR 136      // halves; 272B rows (16 mod 128): conflict-free
#define KELE (FBN * KSTR)
#define VELE (FBN * VSTR)
#define FLASH_SMEM (2 * (KELE + VELE) * 2)

__global__ __launch_bounds__(256) void flash_k(
    const __half* __restrict__ QH_g, const __half* __restrict__ KVH_g,
    const __half* __restrict__ KPEH_g, __half* __restrict__ OH)
{
    extern __shared__ __half smf[];
    const uint32_t sbase = smem_u32(smf);

    const int q0 = blockIdx.x * FBM;
    const int h = blockIdx.y;
    const int b = blockIdx.z;
    const int t = threadIdx.x;
    const int warp = t >> 5;
    const int lane = t & 31;
    const int g = lane >> 2;
    const int tg = lane & 3;
    const int row0 = warp * 16 + g;
    const float scale = rsqrtf((float)QH);

    const int lm = lane >> 3, lr8 = lane & 7;
    const int kRowOff = (lm >> 1) * 8 + lr8;
    const int kKOff   = (lm & 1) * 8;
    const int vK      = (lm & 1) * 8 + lr8;
    const int vC      = (lm >> 1) * 8;

    unsigned aq[12][4];
    {
        const unsigned* qp0 = (const unsigned*)(QH_g + ((size_t)(b * SS + q0 + row0) * HH + h) * QH);
        const unsigned* qp1 = qp0 + (size_t)8 * HH * QH / 2;
#pragma unroll
        for (int kc = 0; kc < 12; kc++) {
            aq[kc][0] = qp0[kc * 8 + tg];
            aq[kc][1] = qp1[kc * 8 + tg];
            aq[kc][2] = qp0[kc * 8 + tg + 4];
            aq[kc][3] = qp1[kc * 8 + tg + 4];
        }
    }

    float oacc[16][4];
#pragma unroll
    for (int i = 0; i < 16; i++)
#pragma unroll
        for (int e = 0; e < 4; e++) oacc[i][e] = 0.f;
    float m0 = -3.0e38f, m1 = -3.0e38f, l0 = 0.f, l1 = 0.f;

    const int flr = t >> 2;
    const int q4 = t & 3;
    const int ntiles = (q0 + FBM) / FBN;

#define FL_LOAD(tt, bufi)                                                          \
    do {                                                                           \
        const int kk0 = (tt) * FBN;                                                \
        const __half* kvrow = KVH_g + ((size_t)(b * SS + kk0 + flr) * HH + h) * KVH;\
        const __half* kprow = KPEH_g + (size_t)(b * SS + kk0 + flr) * ROPE_D;      \
        const uint32_t kdst = sbase + (bufi) * (KELE * 2) + flr * (KSTR * 2);      \
        const uint32_t vdst = sbase + 2 * (KELE * 2) + (bufi) * (VELE * 2)         \
                              + flr * (VSTR * 2);                                  \
        _Pragma("unroll")                                                          \
        for (int i = 0; i < 6; i++) {                                              \
            int c = q4 * 6 + i;                                                    \
            const __half* src = (c < 16) ? kvrow + c * 8 : kprow + (c - 16) * 8;   \
            cpa16(kdst + c * 16, src);                                             \
        }                                                                          \
        _Pragma("unroll")                                                          \
        for (int i = 0; i < 4; i++) {                                              \
            int c = q4 * 4 + i;                                                    \
            cpa16(vdst + c * 16, kvrow + 128 + c * 8);                             \
        }                                                                          \
        CP_COMMIT();                                                               \
    } while (0)

    FL_LOAD(0, 0);

    for (int tile = 0; tile < ntiles; tile++) {
        const int k0 = tile * FBN;
        const int buf = tile & 1;
        if (tile + 1 < ntiles) {
            FL_LOAD(tile + 1, buf ^ 1);
            CP_WAIT(1);
        } else {
            CP_WAIT(0);
        }
        __syncthreads();

        if (k0 <= q0 + warp * 16 + 15) {
            const uint32_t kb2 = sbase + buf * (KELE * 2);
            const uint32_t vb = sbase + 2 * (KELE * 2) + buf * (VELE * 2);

            float c[8][4];
#pragma unroll
            for (int nb = 0; nb < 8; nb++)
#pragma unroll
                for (int e = 0; e < 4; e++) c[nb][e] = 0.f;
#pragma unroll
            for (int kc = 0; kc < 12; kc++) {
#pragma unroll
                for (int n16 = 0; n16 < 4; n16++) {
                    uint32_t a = kb2 + (uint32_t)(((n16 * 16 + kRowOff) * KSTR
                                                  + kc * 16 + kKOff) * 2);
                    unsigned b0, b1, b2, b3;
                    ldmx4(b0, b1, b2, b3, a);
                    unsigned bf0[2] = {b0, b1};
                    unsigned bf1[2] = {b2, b3};
                    mma_f16(c[2 * n16], aq[kc], bf0);
                    mma_f16(c[2 * n16 + 1], aq[kc], bf1);
                }
            }
#pragma unroll
            for (int nb = 0; nb < 8; nb++)
#pragma unroll
                for (int e = 0; e < 4; e++) c[nb][e] *= scale;

            if (k0 + FBN - 1 > q0 + warp * 16) {
                const int r0g = q0 + warp * 16 + g;
#pragma unroll
                for (int nb = 0; nb < 8; nb++) {
                    int col = k0 + nb * 8 + 2 * tg;
                    if (col     > r0g)     c[nb][0] = -3.0e38f;
                    if (col + 1 > r0g)     c[nb][1] = -3.0e38f;
                    if (col     > r0g + 8) c[nb][2] = -3.0e38f;
                    if (col + 1 > r0g + 8) c[nb][3] = -3.0e38f;
                }
            }

            float tm0 = -3.0e38f, tm1 = -3.0e38f;
#pragma unroll
            for (int nb = 0; nb < 8; nb++) {
                tm0 = fmaxf(tm0, fmaxf(c[nb][0], c[nb][1]));
                tm1 = fmaxf(tm1, fmaxf(c[nb][2], c[nb][3]));
            }
            tm0 = fmaxf(tm0, __shfl_xor_sync(0xffffffffu, tm0, 1));
            tm0 = fmaxf(tm0, __shfl_xor_sync(0xffffffffu, tm0, 2));
            tm1 = fmaxf(tm1, __shfl_xor_sync(0xffffffffu, tm1, 1));
            tm1 = fmaxf(tm1, __shfl_xor_sync(0xffffffffu, tm1, 2));

            float nm0 = fmaxf(m0, tm0), nm1 = fmaxf(m1, tm1);
            float co0 = __expf(m0 - nm0), co1 = __expf(m1 - nm1);
            l0 *= co0; l1 *= co1;
#pragma unroll
            for (int nb = 0; nb < 16; nb++) {
                oacc[nb][0] *= co0; oacc[nb][1] *= co0;
                oacc[nb][2] *= co1; oacc[nb][3] *= co1;
            }
            m0 = nm0; m1 = nm1;

            float ls0 = 0.f, ls1 = 0.f;
#pragma unroll
            for (int nb = 0; nb < 8; nb++) {
                c[nb][0] = __expf(c[nb][0] - nm0);
                c[nb][1] = __expf(c[nb][1] - nm0);
                c[nb][2] = __expf(c[nb][2] - nm1);
                c[nb][3] = __expf(c[nb][3] - nm1);
                ls0 += c[nb][0] + c[nb][1];
                ls1 += c[nb][2] + c[nb][3];
            }
            ls0 += __shfl_xor_sync(0xffffffffu, ls0, 1);
            ls0 += __shfl_xor_sync(0xffffffffu, ls0, 2);
            ls1 += __shfl_xor_sync(0xffffffffu, ls1, 1);
            ls1 += __shfl_xor_sync(0xffffffffu, ls1, 2);
            l0 += ls0; l1 += ls1;

#pragma unroll
            for (int kr = 0; kr < 4; kr++) {
                unsigned ap[4];
                ap[0] = h2u(c[2 * kr][0],     c[2 * kr][1]);
                ap[1] = h2u(c[2 * kr][2],     c[2 * kr][3]);
                ap[2] = h2u(c[2 * kr + 1][0], c[2 * kr + 1][1]);
                ap[3] = h2u(c[2 * kr + 1][2], c[2 * kr + 1][3]);
                const uint32_t krowb = vb + (uint32_t)((kr * 16 + vK) * (VSTR * 2));
#pragma unroll
                for (int np = 0; np < 8; np++) {
                    uint32_t a = krowb + (uint32_t)((np * 16 + vC) * 2);
                    unsigned b0, b1, b2, b3;
                    ldmx4t(b0, b1, b2, b3, a);
                    unsigned bv0[2] = {b0, b1};
                    unsigned bv1[2] = {b2, b3};
                    mma_f16(oacc[2 * np], ap, bv0);
                    mma_f16(oacc[2 * np + 1], ap, bv1);
                }
            }
        }
        __syncthreads();
    }

    float inv0 = 1.f / l0, inv1 = 1.f / l1;
    __half* o0 = OH + ((size_t)(b * SS + q0 + row0) * HH + h) * VD;
    __half* o1 = o0 + (size_t)8 * HH * VD;
#pragma unroll
    for (int nb = 0; nb < 16; nb++) {
        *(unsigned*)(o0 + nb * 8 + 2 * tg) = h2u(oacc[nb][0] * inv0, oacc[nb][1] * inv0);
        *(unsigned*)(o1 + nb * 8 + 2 * tg) = h2u(oacc[nb][2] * inv1, oacc[nb][3] * inv1);
    }
}

// ---------------- host launcher ------------------------------------------
extern "C" void kernel_launch(void* const* d_in, const int* in_sizes, int n_in,
                              void* d_out, int out_size)
{
    const float* x         = (const float*)d_in[0];
    const float* w_dq      = (const float*)d_in[1];
    const float* q_a_norm  = (const float*)d_in[2];
    const float* w_uq      = (const float*)d_in[3];
    const float* w_dkv     = (const float*)d_in[4];
    const float* kv_a_norm = (const float*)d_in[5];
    const float* w_ukv     = (const float*)d_in[6];
    const float* w_o       = (const float*)d_in[7];
    float* out = (float*)d_out;

    float *c1, *ct, *st;
    __half *xh, *w1T, *wuqT, *wukvT, *woT, *cqh, *kvah, *oh, *qh, *kvh, *kpeh;
    cudaGetSymbolAddress((void**)&c1,  g_c1);
    cudaGetSymbolAddress((void**)&ct,  g_cos);
    cudaGetSymbolAddress((void**)&st,  g_sin);
    cudaGetSymbolAddress((void**)&xh,    g_xh);
    cudaGetSymbolAddress((void**)&w1T,   g_w1T);
    cudaGetSymbolAddress((void**)&wuqT,  g_wuqT);
    cudaGetSymbolAddress((void**)&wukvT, g_wukvT);
    cudaGetSymbolAddress((void**)&woT,   g_woT);
    cudaGetSymbolAddress((void**)&cqh,   g_cqh);
    cudaGetSymbolAddress((void**)&kvah,  g_kvah);
    cudaGetSymbolAddress((void**)&oh,    g_oh);
    cudaGetSymbolAddress((void**)&qh,    g_qh);
    cudaGetSymbolAddress((void**)&kvh,   g_kvh);
    cudaGetSymbolAddress((void**)&kpeh,  g_kpeh);

    cudaFuncSetAttribute(hgemm_k,  cudaFuncAttributeMaxDynamicSharedMemorySize, HG_SMEM);
    cudaFuncSetAttribute(hgemmh_k, cudaFuncAttributeMaxDynamicSharedMemorySize, HG_SMEM);
    cudaFuncSetAttribute(flash_k,  cudaFuncAttributeMaxDynamicSharedMemorySize, FLASH_SMEM);

    rope_table_k<<<SS, 32>>>(ct, st);

    // convert x; transpose+convert weights. w_dq and w_dkv land in one
    // merged [N1][DD] buffer (rows 0..1535 and 1536..2111).
    cvth_k<<<592, 256>>>((const float4*)x, xh, RTOT * DD / 4);
    trth_k<<<dim3(Q_RANK / 32, DD / 32), 256>>>(w_dq, w1T, DD, Q_RANK);
    trth_k<<<dim3((KV_RANK + ROPE_D) / 32, DD / 32), 256>>>(
        w_dkv, w1T + (size_t)Q_RANK * DD, DD, KV_RANK + ROPE_D);
    trth_k<<<dim3((HH * QH) / 32, Q_RANK / 32), 256>>>(w_uq, wuqT, Q_RANK, HH * QH);
    trth_k<<<dim3((HH * KVH) / 32, KV_RANK / 32), 256>>>(w_ukv, wukvT, KV_RANK, HH * KVH);
    trth_k<<<dim3(DD / 32, (HH * VD) / 32), 256>>>(w_o, woT, HH * VD, DD);

    // merged x-projection: c1[:, 0:1536] = x@w_dq, c1[:, 1536:2112] = x@w_dkv
    hgemm_k<<<dim3((N1 + 127) / 128, RTOT / 128), 128, HG_SMEM>>>(xh, w1T, c1, RTOT, N1, DD);

    // norms (strided reads from merged buffer)
    rmsnorm_k<<<RTOT, 256>>>(c1, cqh, q_a_norm, Q_RANK, N1, Q_RANK);
    rmsnorm_k<<<RTOT, 256>>>(c1 + Q_RANK, kvah, kv_a_norm, KV_RANK, N1, KV_RANK);

    // up-projections (fp16 out, feed flash)
    hgemmh_k<<<dim3((HH * QH) / 128, RTOT / 128), 128, HG_SMEM>>>(cqh, wuqT, qh, RTOT, HH * QH, Q_RANK);
    hgemmh_k<<<dim3((HH * KVH) / 128, RTOT / 128), 128, HG_SMEM>>>(kvah, wukvT, kvh, RTOT, HH * KVH, KV_RANK);

    // RoPE: q in-place on half; k_pe from merged fp32 buffer -> half
    rope_qh_k<<<RTOT, dim3(32, HH)>>>(qh, ct, st);
    rope_kh_k<<<RTOT, 32>>>(c1 + Q_RANK + KV_RANK, N1, kpeh, ct, st);

    // attention
    flash_k<<<dim3(SS / FBM, HH, BB), 256, FLASH_SMEM>>>(qh, kvh, kpeh, oh);

    // output projection
    hgemm_k<<<dim3(DD / 128, RTOT / 128), 128, HG_SMEM>>>(oh, woT, out, RTOT, DD, HH * VD);
}